// round 13
// baseline (speedup 1.0000x reference)
#include <cuda_runtime.h>
#include <cuda_fp16.h>
#include <mma.h>
#include <math.h>
#include <stdint.h>

using namespace nvcuda;
typedef __half fp16;
constexpr int C_=1024, S_=784, M_=6272, HID_=4096, BC_=512, G_=128;

__device__ __align__(16) fp16 g_xnh[M_*C_], g_xnl[M_*C_];
__device__ __align__(16) float g_qkv[M_*3*C_];
__device__ __align__(16) fp16 g_qh[G_*S_*64], g_ql[G_*S_*64], g_kh[G_*S_*64];
__device__ __align__(16) fp16 g_vTh[G_*64*S_];
__device__ __align__(16) float g_bh[G_*S_*28], g_bw[G_*S_*28];
__device__ __align__(16) fp16 g_attn[(size_t)G_*S_*S_];
__device__ __align__(16) fp16 g_aoh[M_*C_], g_aol[M_*C_];
__device__ __align__(16) float g_x1[M_*C_];
__device__ __align__(16) fp16 g_mh[M_*HID_], g_ml[M_*HID_];
__device__ __align__(16) float g_x2[M_*C_];
__device__ __align__(16) fp16 g_x2h[M_*C_], g_x2l[M_*C_];
__device__ __align__(16) float g_c1[M_*BC_];
__device__ __align__(16) fp16 g_c1h[M_*BC_], g_c1l[M_*BC_];
__device__ __align__(16) float g_c2[M_*BC_];
__device__ __align__(16) fp16 g_c2h[M_*BC_], g_c2l[M_*BC_];
__device__ __align__(16) float g_c3[M_*C_];
__device__ __align__(16) fp16 g_wah[3*C_*C_];
__device__ __align__(16) fp16 g_wbh[C_*C_];
__device__ __align__(16) fp16 g_wch[HID_*C_];
__device__ __align__(16) fp16 g_wdh[C_*HID_];
__device__ __align__(16) fp16 g_weh[BC_*C_];
__device__ __align__(16) fp16 g_wfh[BC_*9*BC_];
__device__ __align__(16) fp16 g_wgh[C_*BC_];

__device__ __forceinline__ float gelu_f(float x){ return 0.5f*x*(1.0f+erff(x*0.7071067811865475f)); }
__device__ __forceinline__ void split2(float x, fp16&h, fp16&l){
    h = __float2half_rn(x); l = __float2half_rn(x - __half2float(h));
}

__device__ __forceinline__ void cp16(fp16* sm, const fp16* gm, bool pred){
    uint32_t sa = (uint32_t)__cvta_generic_to_shared(sm);
    int sz = pred ? 16 : 0;
    asm volatile("cp.async.ca.shared.global [%0], [%1], 16, %2;" :: "r"(sa), "l"(gm), "r"(sz));
}
#define CP_COMMIT() asm volatile("cp.async.commit_group;")

__device__ __forceinline__ void stage_tile(const fp16* __restrict__ src, int ld,
        int row0, int rmax, int k0, int K, fp16* sm, int tid, int rows){
    for (int i = tid; i < rows*4; i += 256){
        int r = i>>2, cq = i&3;
        int gr = row0 + r, gk = k0 + (cq<<3);
        bool p = (gr < rmax && gk < K);
        cp16(sm + r*40 + (cq<<3), p ? src + (size_t)gr*ld + gk : src, p);
    }
}
__device__ __forceinline__ void stage_conv(const fp16* __restrict__ src, int row0, int k0,
        fp16* sm, int tid){
    int ky = k0/1536, kxr = k0 - ky*1536, kx = kxr>>9, ci0 = kxr&511;
    for (int i = tid; i < 512; i += 256){
        int r = i>>2, cq = i&3;
        int gr = row0 + r;
        bool p = false; const fp16* g = src;
        if (gr < M_){
            int b = gr/S_, rem = gr - b*S_, h = rem/28, w = rem - h*28;
            int ih = h+ky-1, iw = w+kx-1;
            if ((unsigned)ih<28u && (unsigned)iw<28u){
                p = true; g = src + ((size_t)((b*28+ih)*28+iw))*BC_ + ci0 + (cq<<3);
            }
        }
        cp16(sm + r*40 + (cq<<3), g, p);
    }
}

// fp16x2 wmma GEMM: D = (Ah+Al)@Bh^T, 2-stage cp.async pipeline. B given as [N,K].
// EPI 0: fp32(+bias)  1: gelu->split  2: +bias+res->fp32
// EPI 3: +bh+bw -> fp16 scores to o1   5: +bias+res->fp32 AND split
template<int BN, int EPI, int GATHER>
__global__ void __launch_bounds__(256) mma_gemm(
    const fp16* __restrict__ Ah, const fp16* __restrict__ Al,
    const fp16* __restrict__ Bh,
    float* __restrict__ o0, fp16* __restrict__ o1, fp16* __restrict__ o2,
    int M, int N, int K, int lda, int ldb, int ldc,
    long long sA, long long sB, long long sC,
    const float* __restrict__ bias, const float* __restrict__ res, int ldres,
    const float* __restrict__ bhp, const float* __restrict__ bwp)
{
    constexpr int BM = 128;
    constexpr int WarpsN = 4, WarpsM = 2;
    constexpr int WM = BM/WarpsM, WN = BN/WarpsN;
    constexpr int MI = WM/16, NI = WN/16;
    constexpr int ATILE = BM*40, BTILE = BN*40;
    constexpr int STAGE = 2*ATILE + BTILE;
    extern __shared__ __align__(128) fp16 pool[];

    const int tid = threadIdx.x, warp = tid>>5, lane = tid&31;
    const int bm = blockIdx.x*BM, bn = blockIdx.y*BN, g = blockIdx.z;
    Ah += (size_t)g*sA; Al += (size_t)g*sA; Bh += (size_t)g*sB;
    const int wrow = (warp/WarpsN)*WM, wcol = (warp%WarpsN)*WN;

    wmma::fragment<wmma::accumulator,16,16,16,float> acc[MI][NI];
    #pragma unroll
    for (int mi=0; mi<MI; mi++)
        #pragma unroll
        for (int ni=0; ni<NI; ni++) wmma::fill_fragment(acc[mi][ni], 0.f);

    const int KC = (K+31)>>5;
    auto issue = [&](int kc, int s){
        fp16* st = pool + s*STAGE;
        int k0 = kc<<5;
        if (GATHER){ stage_conv(Ah, bm, k0, st, tid); stage_conv(Al, bm, k0, st+ATILE, tid); }
        else { stage_tile(Ah, lda, bm, M, k0, K, st, tid, BM);
               stage_tile(Al, lda, bm, M, k0, K, st+ATILE, tid, BM); }
        stage_tile(Bh, ldb, bn, N, k0, K, st+2*ATILE, tid, BN);
        CP_COMMIT();
    };
    issue(0, 0);
    for (int kc = 0; kc < KC; kc++){
        int buf = kc & 1;
        if (kc+1 < KC){
            issue(kc+1, buf^1);
            asm volatile("cp.async.wait_group 1;");
        } else {
            asm volatile("cp.async.wait_group 0;");
        }
        __syncthreads();
        fp16 *Ash = pool + buf*STAGE, *Asl = Ash + ATILE, *Bsh = Ash + 2*ATILE;
        #pragma unroll
        for (int ks=0; ks<2; ks++){
            wmma::fragment<wmma::matrix_b,16,16,16,fp16,wmma::col_major> bh_f[NI];
            #pragma unroll
            for (int ni=0; ni<NI; ni++)
                wmma::load_matrix_sync(bh_f[ni], Bsh + (wcol+ni*16)*40 + ks*16, 40);
            #pragma unroll
            for (int mi=0; mi<MI; mi++){
                wmma::fragment<wmma::matrix_a,16,16,16,fp16,wmma::row_major> ah_f, al_f;
                wmma::load_matrix_sync(ah_f, Ash + (wrow+mi*16)*40 + ks*16, 40);
                wmma::load_matrix_sync(al_f, Asl + (wrow+mi*16)*40 + ks*16, 40);
                #pragma unroll
                for (int ni=0; ni<NI; ni++){
                    wmma::mma_sync(acc[mi][ni], ah_f, bh_f[ni], acc[mi][ni]);
                    wmma::mma_sync(acc[mi][ni], al_f, bh_f[ni], acc[mi][ni]);
                }
            }
        }
        __syncthreads();
    }

    float* eb = reinterpret_cast<float*>(pool) + warp*320;   // 16x20
    #pragma unroll
    for (int mi=0; mi<MI; mi++){
        #pragma unroll
        for (int ni=0; ni<NI; ni++){
            wmma::store_matrix_sync(eb, acc[mi][ni], 20, wmma::mem_row_major);
            __syncwarp();
            int row0 = bm + wrow + mi*16, col0 = bn + wcol + ni*16;
            #pragma unroll
            for (int j=0; j<8; j++){
                int e = lane + j*32, r = e>>4, c = e&15;
                int gr = row0 + r, gc = col0 + c;
                if (gr < M && gc < N){
                    float v = eb[r*20 + c];
                    if (bias) v += bias[gc];
                    if (EPI == 1){ v = gelu_f(v); fp16 h,l; split2(v,h,l);
                        o1[(size_t)gr*ldc+gc]=h; o2[(size_t)gr*ldc+gc]=l; }
                    else if (EPI == 2){ o0[(size_t)gr*ldc+gc] = v + res[(size_t)gr*ldres+gc]; }
                    else if (EPI == 3){
                        v += bhp[((size_t)g*S_+gr)*28 + gc/28] + bwp[((size_t)g*S_+gr)*28 + gc%28];
                        o1[(size_t)g*sC + (size_t)gr*ldc + gc] = __float2half_rn(v); }
                    else if (EPI == 5){ v += res[(size_t)gr*ldres+gc];
                        o0[(size_t)gr*ldc+gc] = v; fp16 h,l; split2(v,h,l);
                        o1[(size_t)gr*ldc+gc]=h; o2[(size_t)gr*ldc+gc]=l; }
                    else o0[(size_t)gr*ldc+gc] = v;
                }
            }
            __syncwarp();
        }
    }
}

// fused stats + softmax + AV on fp16 scores
__global__ void __launch_bounds__(256) av_k(
    const fp16* __restrict__ attn,
    const fp16* __restrict__ vT, fp16* __restrict__ oh, fp16* __restrict__ ol)
{
    constexpr int KC = 25;
    __shared__ __align__(16) fp16 Ph[2][128*40], Pl[2][128*40], Vs[2][64*40];
    __shared__ float2 st[128];
    const int tid = threadIdx.x, warp = tid>>5, lane = tid&31;
    const int bm = blockIdx.x*128, g = blockIdx.y;
    attn += (size_t)g*S_*S_;
    vT   += (size_t)g*64*S_;
    const int wrow = (warp>>1)*32, wcol = (warp&1)*32;

    stage_tile(vT, S_, 0, 64, 0, S_, Vs[0], tid, 64);
    CP_COMMIT();

    // phase 0: per-row softmax stats
    for (int rr = 0; rr < 16; rr++){
        int r = warp*16 + rr;
        int grow = bm + r;
        float vbuf[25];
        float m = -1e30f;
        if (grow < S_){
            const fp16* p = attn + (size_t)grow*S_;
            #pragma unroll
            for (int i=0;i<25;i++){
                int col = lane + i*32;
                vbuf[i] = (col < S_) ? __half2float(p[col]) : -1e30f;
                m = fmaxf(m, vbuf[i]);
            }
        } else {
            #pragma unroll
            for (int i=0;i<25;i++) vbuf[i] = -1e30f;
        }
        #pragma unroll
        for (int o=16;o;o>>=1) m = fmaxf(m, __shfl_xor_sync(~0u, m, o));
        float s = 0.f;
        if (grow < S_){
            #pragma unroll
            for (int i=0;i<25;i++){
                int col = lane + i*32;
                if (col < S_) s += __expf(vbuf[i] - m);
            }
        }
        #pragma unroll
        for (int o=16;o;o>>=1) s += __shfl_xor_sync(~0u, s, o);
        if (lane == 0)
            st[r] = (grow < S_) ? make_float2(m, 1.f/s) : make_float2(0.f, 0.f);
    }

    wmma::fragment<wmma::accumulator,16,16,16,float> acc[2][2];
    #pragma unroll
    for (int mi=0; mi<2; mi++)
        #pragma unroll
        for (int ni=0; ni<2; ni++) wmma::fill_fragment(acc[mi][ni], 0.f);

    uint2 areg[4];   // 4 halves each
    auto loadA = [&](int kc){
        int k0 = kc<<5;
        #pragma unroll
        for (int j=0; j<4; j++){
            int s = tid + j*256, r = s>>3, cq = s&7;
            int row = bm + r, col = k0 + cq*4;
            if (row < S_ && col+3 < S_)
                areg[j] = *reinterpret_cast<const uint2*>(attn + (size_t)row*S_ + col);
            else if (row < S_){
                union { fp16 h[4]; uint2 u; } t;
                #pragma unroll
                for (int u=0; u<4; u++)
                    t.h[u] = (col+u < S_) ? attn[(size_t)row*S_ + col+u] : (fp16)0.f;
                areg[j] = t.u;
            } else areg[j] = make_uint2(0,0);
        }
    };
    loadA(0);
    __syncthreads();   // st[] ready

    for (int kc = 0; kc < KC; kc++){
        int buf = kc & 1;
        #pragma unroll
        for (int j=0; j<4; j++){
            int s = tid + j*256, r = s>>3, cq = s&7;
            float m = st[r].x, inv = st[r].y;
            bool rv = (bm + r) < S_;
            union { fp16 h[4]; uint2 u; } av;
            av.u = areg[j];
            union { fp16 h[4]; uint2 u; } ph, pl;
            #pragma unroll
            for (int u=0; u<4; u++){
                int col = (kc<<5) + cq*4 + u;
                float p = (rv && col < S_) ? __expf(__half2float(av.h[u]) - m) * inv : 0.f;
                split2(p, ph.h[u], pl.h[u]);
            }
            *reinterpret_cast<uint2*>(&Ph[buf][r*40 + cq*4]) = ph.u;
            *reinterpret_cast<uint2*>(&Pl[buf][r*40 + cq*4]) = pl.u;
        }
        if (kc+1 < KC){
            loadA(kc+1);
            stage_tile(vT, S_, 0, 64, (kc+1)<<5, S_, Vs[buf^1], tid, 64);
            CP_COMMIT();
            asm volatile("cp.async.wait_group 1;");
        } else {
            asm volatile("cp.async.wait_group 0;");
        }
        __syncthreads();
        #pragma unroll
        for (int ks=0; ks<2; ks++){
            wmma::fragment<wmma::matrix_b,16,16,16,fp16,wmma::col_major> b_f[2];
            #pragma unroll
            for (int ni=0; ni<2; ni++)
                wmma::load_matrix_sync(b_f[ni], Vs[buf] + (wcol+ni*16)*40 + ks*16, 40);
            #pragma unroll
            for (int mi=0; mi<2; mi++){
                wmma::fragment<wmma::matrix_a,16,16,16,fp16,wmma::row_major> ah_f, al_f;
                wmma::load_matrix_sync(ah_f, Ph[buf] + (wrow+mi*16)*40 + ks*16, 40);
                wmma::load_matrix_sync(al_f, Pl[buf] + (wrow+mi*16)*40 + ks*16, 40);
                #pragma unroll
                for (int ni=0; ni<2; ni++){
                    wmma::mma_sync(acc[mi][ni], ah_f, b_f[ni], acc[mi][ni]);
                    wmma::mma_sync(acc[mi][ni], al_f, b_f[ni], acc[mi][ni]);
                }
            }
        }
        __syncthreads();
    }

    float* eb = reinterpret_cast<float*>(Ph) + warp*320;
    #pragma unroll
    for (int mi=0; mi<2; mi++){
        #pragma unroll
        for (int ni=0; ni<2; ni++){
            wmma::store_matrix_sync(eb, acc[mi][ni], 20, wmma::mem_row_major);
            __syncwarp();
            int row0 = bm + wrow + mi*16, col0 = wcol + ni*16;
            #pragma unroll
            for (int j=0; j<8; j++){
                int e = lane + j*32, r = e>>4, c = e&15;
                int gr = row0 + r, gc = col0 + c;
                if (gr < S_){
                    size_t o = ((size_t)(g>>4)*S_ + gr)*1024 + (size_t)(g&15)*64 + gc;
                    fp16 h,l; split2(eb[r*20 + c], h, l);
                    oh[o]=h; ol[o]=l;
                }
            }
            __syncwarp();
        }
    }
}

__global__ void ln_k(const float* __restrict__ x, const float* __restrict__ w,
                     const float* __restrict__ bp, float* __restrict__ of,
                     fp16* __restrict__ oh, fp16* __restrict__ ol,
                     int Cw, float eps, int mode, const float* __restrict__ res)
{
    __shared__ float r1[8], r2[8], st[2];
    const int row = blockIdx.x, tid = threadIdx.x, lane = tid&31, wd = tid>>5;
    const float* xr = x + (size_t)row*Cw;
    float s=0.f, sq=0.f;
    for (int i = tid; i < Cw; i += 256){ float t = xr[i]; s += t; sq += t*t; }
    #pragma unroll
    for (int o=16;o;o>>=1){ s+=__shfl_down_sync(~0u,s,o); sq+=__shfl_down_sync(~0u,sq,o); }
    if (lane==0){ r1[wd]=s; r2[wd]=sq; }
    __syncthreads();
    if (tid==0){ float S=0,Q=0; for(int i=0;i<8;i++){S+=r1[i];Q+=r2[i];}
        float m=S/Cw, v=Q/Cw-m*m; st[0]=m; st[1]=rsqrtf(v+eps); }
    __syncthreads();
    float mean=st[0], rstd=st[1];
    for (int i = tid; i < Cw; i += 256){
        float y = (xr[i]-mean)*rstd*w[i] + bp[i];
        if (mode==2) of[(size_t)row*Cw+i] = y + res[(size_t)row*Cw+i];
        else { if (mode==1) y = gelu_f(y);
            fp16 h,l; split2(y,h,l); oh[(size_t)row*Cw+i]=h; ol[(size_t)row*Cw+i]=l; }
    }
}

__global__ void repack_k(const float* __restrict__ qkv,
    fp16* __restrict__ qh, fp16* __restrict__ ql, fp16* __restrict__ kh,
    fp16* __restrict__ vTh)
{
    __shared__ float sv[32][65];
    const int g = blockIdx.y, s0 = blockIdx.x*32, b = g>>4, n = g&15, t = threadIdx.x;
    for (int e = t; e < 2048; e += 256){
        int sl = e>>6, d = e&63, s = s0+sl;
        if (s < S_){
            size_t base = ((size_t)(b*S_+s))*3072 + n*64 + d;
            float qv = qkv[base]*0.125f;
            sv[sl][d] = qkv[base+2048];
            size_t o = ((size_t)g*S_+s)*64 + d;
            fp16 h,l; split2(qv,h,l); qh[o]=h; ql[o]=l;
            kh[o] = __float2half_rn(qkv[base+1024]);
        }
    }
    __syncthreads();
    for (int e = t; e < 2048; e += 256){
        int d = e>>5, j = e&31, s = s0+j;
        if (s < S_)
            vTh[((size_t)g*64+d)*S_ + s] = __float2half_rn(sv[j][d]);
    }
}

__global__ void relbias_k(const float* __restrict__ qkv, const float* __restrict__ rh,
                          const float* __restrict__ rw, float* __restrict__ bh, float* __restrict__ bw)
{
    const int s = blockIdx.x % S_, g = blockIdx.x / S_, b = g>>4, n = g&15;
    __shared__ float qs[64];
    const int t = threadIdx.x;
    qs[t] = qkv[((size_t)(b*S_+s))*3072 + n*64 + t];
    __syncthreads();
    const int h = s/28, w = s%28;
    if (t < 28){
        const float* r = rh + (size_t)(h-t+27)*64; float a=0.f;
        #pragma unroll
        for (int d=0;d<64;d++) a = fmaf(qs[d], r[d], a);
        bh[((size_t)g*S_+s)*28 + t] = a;
    } else if (t >= 32 && t < 60){
        const int l = t-32;
        const float* r = rw + (size_t)(w-l+27)*64; float a=0.f;
        #pragma unroll
        for (int d=0;d<64;d++) a = fmaf(qs[d], r[d], a);
        bw[((size_t)g*S_+s)*28 + l] = a;
    }
}

__global__ void wsplit_all(
    const float* s0, const float* s1, const float* s2, const float* s3,
    const float* s4, const float* s5, const float* s6,
    fp16* d0, fp16* d1, fp16* d2, fp16* d3, fp16* d4, fp16* d5, fp16* d6)
{
    int t = blockIdx.x;
    const float* src; fp16* dst; int K, N, loc;
    if      (t <  3072){ src=s0; dst=d0; K=C_;     N=3*C_;  loc=t; }
    else if (t <  4096){ src=s1; dst=d1; K=C_;     N=C_;    loc=t-3072; }
    else if (t <  8192){ src=s2; dst=d2; K=C_;     N=HID_;  loc=t-4096; }
    else if (t < 12288){ src=s3; dst=d3; K=HID_;   N=C_;    loc=t-8192; }
    else if (t < 12800){ src=s4; dst=d4; K=C_;     N=BC_;   loc=t-12288; }
    else if (t < 15104){ src=s5; dst=d5; K=9*BC_;  N=BC_;   loc=t-12800; }
    else               { src=s6; dst=d6; K=BC_;    N=C_;    loc=t-15104; }
    int kt = K >> 5;
    int k0 = (loc % kt) * 32, n0 = (loc / kt) * 32;

    __shared__ float s[32][33];
    const int tx = threadIdx.x, ty = threadIdx.y;
    #pragma unroll
    for (int y=0;y<32;y+=8) s[ty+y][tx] = src[(size_t)(k0+ty+y)*N + n0+tx];
    __syncthreads();
    #pragma unroll
    for (int y=0;y<32;y+=8)
        dst[(size_t)(n0+ty+y)*K + k0+tx] = __float2half_rn(s[tx][ty+y]);
}

constexpr int SM128 = (2*128*40 + 128*40)*2*2;   // 61440 B
#define GSA(p, sym) cudaGetSymbolAddress((void**)&p, sym)
extern "C" void kernel_launch(void* const* d_in, const int* in_sizes, int n_in,
                              void* d_out, int out_size)
{
    const float *x=(const float*)d_in[0], *n1w=(const float*)d_in[1], *n1b=(const float*)d_in[2],
        *qkvw=(const float*)d_in[3], *qkvb=(const float*)d_in[4], *pw=(const float*)d_in[5],
        *pb=(const float*)d_in[6], *relh=(const float*)d_in[7], *relw=(const float*)d_in[8],
        *n2w=(const float*)d_in[9], *n2b=(const float*)d_in[10], *f1w=(const float*)d_in[11],
        *f1b=(const float*)d_in[12], *f2w=(const float*)d_in[13], *f2b=(const float*)d_in[14],
        *c1w=(const float*)d_in[15], *l1w=(const float*)d_in[16], *l1b=(const float*)d_in[17],
        *c2w=(const float*)d_in[18], *l2w=(const float*)d_in[19], *l2b=(const float*)d_in[20],
        *c3w=(const float*)d_in[21], *l3w=(const float*)d_in[22], *l3b=(const float*)d_in[23];
    float* out = (float*)d_out;

    float *qkv,*bh,*bw,*x1,*x2,*c1,*c2,*c3;
    fp16 *attn;
    fp16 *xnh,*xnl,*qh,*ql,*kh,*vTh,*aoh,*aol,*mh,*ml,*x2h,*x2l,*c1h,*c1l,*c2h,*c2l;
    fp16 *wah,*wbh,*wch,*wdh,*weh,*wfh,*wgh;
    GSA(qkv,g_qkv); GSA(bh,g_bh); GSA(bw,g_bw); GSA(attn,g_attn); GSA(x1,g_x1); GSA(x2,g_x2);
    GSA(c1,g_c1); GSA(c2,g_c2); GSA(c3,g_c3);
    GSA(xnh,g_xnh); GSA(xnl,g_xnl); GSA(qh,g_qh); GSA(ql,g_ql); GSA(kh,g_kh);
    GSA(vTh,g_vTh); GSA(aoh,g_aoh); GSA(aol,g_aol);
    GSA(mh,g_mh); GSA(ml,g_ml); GSA(x2h,g_x2h); GSA(x2l,g_x2l);
    GSA(c1h,g_c1h); GSA(c1l,g_c1l); GSA(c2h,g_c2h); GSA(c2l,g_c2l);
    GSA(wah,g_wah); GSA(wbh,g_wbh); GSA(wch,g_wch); GSA(wdh,g_wdh);
    GSA(weh,g_weh); GSA(wfh,g_wfh); GSA(wgh,g_wgh);

    cudaFuncSetAttribute(mma_gemm<128,0,0>, cudaFuncAttributeMaxDynamicSharedMemorySize, SM128);
    cudaFuncSetAttribute(mma_gemm<128,1,0>, cudaFuncAttributeMaxDynamicSharedMemorySize, SM128);
    cudaFuncSetAttribute(mma_gemm<128,2,0>, cudaFuncAttributeMaxDynamicSharedMemorySize, SM128);
    cudaFuncSetAttribute(mma_gemm<128,3,0>, cudaFuncAttributeMaxDynamicSharedMemorySize, SM128);
    cudaFuncSetAttribute(mma_gemm<128,5,0>, cudaFuncAttributeMaxDynamicSharedMemorySize, SM128);
    cudaFuncSetAttribute(mma_gemm<128,0,1>, cudaFuncAttributeMaxDynamicSharedMemorySize, SM128);

    wsplit_all<<<15616, dim3(32,8)>>>(qkvw, pw, f1w, f2w, c1w, c2w, c3w,
                                      wah, wbh, wch, wdh, weh, wfh, wgh);

    ln_k<<<M_,256>>>(x, n1w, n1b, nullptr, xnh, xnl, C_, 1e-5f, 0, nullptr);
    mma_gemm<128,0,0><<<dim3(49,24,1),256,SM128>>>(xnh,xnl,wah, qkv,nullptr,nullptr,
        M_,3*C_,C_, C_,C_,3*C_, 0,0,0, qkvb,nullptr,0,nullptr,nullptr);
    repack_k<<<dim3(25,G_),256>>>(qkv,qh,ql,kh,vTh);
    relbias_k<<<G_*S_,64>>>(qkv,relh,relw,bh,bw);
    mma_gemm<128,3,0><<<dim3(7,7,G_),256,SM128>>>(qh,ql,kh, nullptr,attn,nullptr,
        S_,S_,64, 64,64,S_, (long long)S_*64,(long long)S_*64,(long long)S_*S_,
        nullptr,nullptr,0,bh,bw);
    av_k<<<dim3(7,G_),256>>>(attn, vTh, aoh, aol);
    mma_gemm<128,2,0><<<dim3(49,8,1),256,SM128>>>(aoh,aol,wbh, x1,nullptr,nullptr,
        M_,C_,C_, C_,C_,C_, 0,0,0, pb,x,C_,nullptr,nullptr);
    ln_k<<<M_,256>>>(x1, n2w, n2b, nullptr, xnh, xnl, C_, 1e-5f, 0, nullptr);
    mma_gemm<128,1,0><<<dim3(49,32,1),256,SM128>>>(xnh,xnl,wch, nullptr,mh,ml,
        M_,HID_,C_, C_,C_,HID_, 0,0,0, f1b,nullptr,0,nullptr,nullptr);
    mma_gemm<128,5,0><<<dim3(49,8,1),256,SM128>>>(mh,ml,wdh, x2,x2h,x2l,
        M_,C_,HID_, HID_,HID_,C_, 0,0,0, f2b,x1,C_,nullptr,nullptr);
    mma_gemm<128,0,0><<<dim3(49,4,1),256,SM128>>>(x2h,x2l,weh, c1,nullptr,nullptr,
        M_,BC_,C_, C_,C_,BC_, 0,0,0, nullptr,nullptr,0,nullptr,nullptr);
    ln_k<<<M_,256>>>(c1, l1w, l1b, nullptr, c1h, c1l, BC_, 1e-6f, 1, nullptr);
    mma_gemm<128,0,1><<<dim3(49,4,1),256,SM128>>>(c1h,c1l,wfh, c2,nullptr,nullptr,
        M_,BC_,9*BC_, 0,9*BC_,BC_, 0,0,0, nullptr,nullptr,0,nullptr,nullptr);
    ln_k<<<M_,256>>>(c2, l2w, l2b, nullptr, c2h, c2l, BC_, 1e-6f, 1, nullptr);
    mma_gemm<128,0,0><<<dim3(49,8,1),256,SM128>>>(c2h,c2l,wgh, c3,nullptr,nullptr,
        M_,C_,BC_, BC_,BC_,C_, 0,0,0, nullptr,nullptr,0,nullptr,nullptr);
    ln_k<<<M_,256>>>(c3, l3w, l3b, out, nullptr, nullptr, C_, 1e-6f, 2, x2);
}

// round 14
// speedup vs baseline: 1.0155x; 1.0155x over previous
#include <cuda_runtime.h>
#include <cuda_fp16.h>
#include <mma.h>
#include <math.h>
#include <stdint.h>

using namespace nvcuda;
typedef __half fp16;
constexpr int C_=1024, S_=784, M_=6272, HID_=4096, BC_=512, G_=128;

__device__ __align__(16) fp16 g_xnh[M_*C_], g_xnl[M_*C_];
__device__ __align__(16) float g_qkv[M_*3*C_];
__device__ __align__(16) fp16 g_qh[G_*S_*64], g_ql[G_*S_*64], g_kh[G_*S_*64];
__device__ __align__(16) fp16 g_vTh[G_*64*S_];
__device__ __align__(16) float g_bh[G_*S_*28], g_bw[G_*S_*28];
__device__ __align__(16) float g_attn[(size_t)G_*S_*S_];
__device__ __align__(16) fp16 g_aoh[M_*C_], g_aol[M_*C_];
__device__ __align__(16) float g_x1[M_*C_];
__device__ __align__(16) fp16 g_mh[M_*HID_], g_ml[M_*HID_];
__device__ __align__(16) float g_x2[M_*C_];
__device__ __align__(16) fp16 g_x2h[M_*C_], g_x2l[M_*C_];
__device__ __align__(16) float g_c1[M_*BC_];
__device__ __align__(16) fp16 g_c1h[M_*BC_], g_c1l[M_*BC_];
__device__ __align__(16) float g_c2[M_*BC_];
__device__ __align__(16) fp16 g_c2h[M_*BC_], g_c2l[M_*BC_];
__device__ __align__(16) float g_c3[M_*C_];
__device__ __align__(16) fp16 g_wah[3*C_*C_];
__device__ __align__(16) fp16 g_wbh[C_*C_];
__device__ __align__(16) fp16 g_wch[HID_*C_];
__device__ __align__(16) fp16 g_wdh[C_*HID_];
__device__ __align__(16) fp16 g_weh[BC_*C_];
__device__ __align__(16) fp16 g_wfh[BC_*9*BC_];
__device__ __align__(16) fp16 g_wgh[C_*BC_];

__device__ __forceinline__ float gelu_f(float x){ return 0.5f*x*(1.0f+erff(x*0.7071067811865475f)); }
__device__ __forceinline__ void split2(float x, fp16&h, fp16&l){
    h = __float2half_rn(x); l = __float2half_rn(x - __half2float(h));
}

__device__ __forceinline__ void cp16(fp16* sm, const fp16* gm, bool pred){
    uint32_t sa = (uint32_t)__cvta_generic_to_shared(sm);
    int sz = pred ? 16 : 0;
    asm volatile("cp.async.ca.shared.global [%0], [%1], 16, %2;" :: "r"(sa), "l"(gm), "r"(sz));
}
#define CP_COMMIT() asm volatile("cp.async.commit_group;")

template<int THREADS>
__device__ __forceinline__ void stage_tile(const fp16* __restrict__ src, int ld,
        int row0, int rmax, int k0, int K, fp16* sm, int tid, int rows){
    for (int i = tid; i < rows*4; i += THREADS){
        int r = i>>2, cq = i&3;
        int gr = row0 + r, gk = k0 + (cq<<3);
        bool p = (gr < rmax && gk < K);
        cp16(sm + r*40 + (cq<<3), p ? src + (size_t)gr*ld + gk : src, p);
    }
}
template<int THREADS>
__device__ __forceinline__ void stage_conv(const fp16* __restrict__ src, int row0, int k0,
        fp16* sm, int tid){
    int ky = k0/1536, kxr = k0 - ky*1536, kx = kxr>>9, ci0 = kxr&511;
    for (int i = tid; i < 512; i += THREADS){
        int r = i>>2, cq = i&3;
        int gr = row0 + r;
        bool p = false; const fp16* g = src;
        if (gr < M_){
            int b = gr/S_, rem = gr - b*S_, h = rem/28, w = rem - h*28;
            int ih = h+ky-1, iw = w+kx-1;
            if ((unsigned)ih<28u && (unsigned)iw<28u){
                p = true; g = src + ((size_t)((b*28+ih)*28+iw))*BC_ + ci0 + (cq<<3);
            }
        }
        cp16(sm + r*40 + (cq<<3), g, p);
    }
}

// fp16x2 wmma GEMM: D = (Ah+Al)@Bh^T, 2-stage cp.async pipeline. B given as [N,K].
// EPI 0: fp32(+bias)  1: gelu->split  2: +bias+res->fp32  3: +bh+bw->fp32
// EPI 5: +bias+res->fp32 AND split
template<int BN, int EPI, int GATHER, int THREADS>
__global__ void __launch_bounds__(THREADS) mma_gemm(
    const fp16* __restrict__ Ah, const fp16* __restrict__ Al,
    const fp16* __restrict__ Bh,
    float* __restrict__ o0, fp16* __restrict__ o1, fp16* __restrict__ o2,
    int M, int N, int K, int lda, int ldb, int ldc,
    long long sA, long long sB, long long sC,
    const float* __restrict__ bias, const float* __restrict__ res, int ldres,
    const float* __restrict__ bhp, const float* __restrict__ bwp)
{
    constexpr int BM = 128;
    constexpr int WarpsN = 4, WarpsM = (THREADS/32)/4;
    constexpr int WM = BM/WarpsM, WN = BN/WarpsN;
    constexpr int MI = WM/16, NI = WN/16;
    constexpr int ATILE = BM*40, BTILE = BN*40;
    constexpr int STAGE = 2*ATILE + BTILE;
    extern __shared__ __align__(128) fp16 pool[];

    const int tid = threadIdx.x, warp = tid>>5, lane = tid&31;
    const int bm = blockIdx.x*BM, bn = blockIdx.y*BN, g = blockIdx.z;
    Ah += (size_t)g*sA; Al += (size_t)g*sA; Bh += (size_t)g*sB;
    const int wrow = (warp/WarpsN)*WM, wcol = (warp%WarpsN)*WN;

    wmma::fragment<wmma::accumulator,16,16,16,float> acc[MI][NI];
    #pragma unroll
    for (int mi=0; mi<MI; mi++)
        #pragma unroll
        for (int ni=0; ni<NI; ni++) wmma::fill_fragment(acc[mi][ni], 0.f);

    const int KC = (K+31)>>5;
    auto issue = [&](int kc, int s){
        fp16* st = pool + s*STAGE;
        int k0 = kc<<5;
        if (GATHER){ stage_conv<THREADS>(Ah, bm, k0, st, tid);
                     stage_conv<THREADS>(Al, bm, k0, st+ATILE, tid); }
        else { stage_tile<THREADS>(Ah, lda, bm, M, k0, K, st, tid, BM);
               stage_tile<THREADS>(Al, lda, bm, M, k0, K, st+ATILE, tid, BM); }
        stage_tile<THREADS>(Bh, ldb, bn, N, k0, K, st+2*ATILE, tid, BN);
        CP_COMMIT();
    };
    issue(0, 0);
    for (int kc = 0; kc < KC; kc++){
        int buf = kc & 1;
        if (kc+1 < KC){
            issue(kc+1, buf^1);
            asm volatile("cp.async.wait_group 1;");
        } else {
            asm volatile("cp.async.wait_group 0;");
        }
        __syncthreads();
        fp16 *Ash = pool + buf*STAGE, *Asl = Ash + ATILE, *Bsh = Ash + 2*ATILE;
        #pragma unroll
        for (int ks=0; ks<2; ks++){
            wmma::fragment<wmma::matrix_b,16,16,16,fp16,wmma::col_major> bh_f[NI];
            #pragma unroll
            for (int ni=0; ni<NI; ni++)
                wmma::load_matrix_sync(bh_f[ni], Bsh + (wcol+ni*16)*40 + ks*16, 40);
            #pragma unroll
            for (int mi=0; mi<MI; mi++){
                wmma::fragment<wmma::matrix_a,16,16,16,fp16,wmma::row_major> ah_f, al_f;
                wmma::load_matrix_sync(ah_f, Ash + (wrow+mi*16)*40 + ks*16, 40);
                wmma::load_matrix_sync(al_f, Asl + (wrow+mi*16)*40 + ks*16, 40);
                #pragma unroll
                for (int ni=0; ni<NI; ni++){
                    wmma::mma_sync(acc[mi][ni], ah_f, bh_f[ni], acc[mi][ni]);
                    wmma::mma_sync(acc[mi][ni], al_f, bh_f[ni], acc[mi][ni]);
                }
            }
        }
        __syncthreads();
    }

    float* eb = reinterpret_cast<float*>(pool) + warp*320;   // 16x20
    #pragma unroll
    for (int mi=0; mi<MI; mi++){
        #pragma unroll
        for (int ni=0; ni<NI; ni++){
            wmma::store_matrix_sync(eb, acc[mi][ni], 20, wmma::mem_row_major);
            __syncwarp();
            int row0 = bm + wrow + mi*16, col0 = bn + wcol + ni*16;
            #pragma unroll
            for (int j=0; j<8; j++){
                int e = lane + j*32, r = e>>4, c = e&15;
                int gr = row0 + r, gc = col0 + c;
                if (gr < M && gc < N){
                    float v = eb[r*20 + c];
                    if (bias) v += bias[gc];
                    if (EPI == 1){ v = gelu_f(v); fp16 h,l; split2(v,h,l);
                        o1[(size_t)gr*ldc+gc]=h; o2[(size_t)gr*ldc+gc]=l; }
                    else if (EPI == 2){ o0[(size_t)gr*ldc+gc] = v + res[(size_t)gr*ldres+gc]; }
                    else if (EPI == 3){
                        v += bhp[((size_t)g*S_+gr)*28 + gc/28] + bwp[((size_t)g*S_+gr)*28 + gc%28];
                        o0[(size_t)g*sC + (size_t)gr*ldc + gc] = v; }
                    else if (EPI == 5){ v += res[(size_t)gr*ldres+gc];
                        o0[(size_t)gr*ldc+gc] = v; fp16 h,l; split2(v,h,l);
                        o1[(size_t)gr*ldc+gc]=h; o2[(size_t)gr*ldc+gc]=l; }
                    else o0[(size_t)gr*ldc+gc] = v;
                }
            }
            __syncwarp();
        }
    }
}

// fused stats + softmax + AV: O[g] = softmax(attn[g]) @ V[g]^T, scatter split
__global__ void __launch_bounds__(256) av_k(
    const float* __restrict__ attn,
    const fp16* __restrict__ vT, fp16* __restrict__ oh, fp16* __restrict__ ol)
{
    constexpr int KC = 25;
    __shared__ __align__(16) fp16 Ph[2][128*40], Pl[2][128*40], Vs[2][64*40];
    __shared__ float2 st[128];
    const int tid = threadIdx.x, warp = tid>>5, lane = tid&31;
    const int bm = blockIdx.x*128, g = blockIdx.y;
    attn += (size_t)g*S_*S_;
    vT   += (size_t)g*64*S_;
    const int wrow = (warp>>1)*32, wcol = (warp&1)*32;

    stage_tile<256>(vT, S_, 0, 64, 0, S_, Vs[0], tid, 64);
    CP_COMMIT();

    for (int rr = 0; rr < 16; rr++){
        int r = warp*16 + rr;
        int grow = bm + r;
        float vbuf[25];
        float m = -1e30f;
        if (grow < S_){
            const float* p = attn + (size_t)grow*S_;
            #pragma unroll
            for (int i=0;i<25;i++){
                int col = lane + i*32;
                vbuf[i] = (col < S_) ? p[col] : -1e30f;
                m = fmaxf(m, vbuf[i]);
            }
        } else {
            #pragma unroll
            for (int i=0;i<25;i++) vbuf[i] = -1e30f;
        }
        #pragma unroll
        for (int o=16;o;o>>=1) m = fmaxf(m, __shfl_xor_sync(~0u, m, o));
        float s = 0.f;
        if (grow < S_){
            #pragma unroll
            for (int i=0;i<25;i++){
                int col = lane + i*32;
                if (col < S_) s += __expf(vbuf[i] - m);
            }
        }
        #pragma unroll
        for (int o=16;o;o>>=1) s += __shfl_xor_sync(~0u, s, o);
        if (lane == 0)
            st[r] = (grow < S_) ? make_float2(m, 1.f/s) : make_float2(0.f, 0.f);
    }

    wmma::fragment<wmma::accumulator,16,16,16,float> acc[2][2];
    #pragma unroll
    for (int mi=0; mi<2; mi++)
        #pragma unroll
        for (int ni=0; ni<2; ni++) wmma::fill_fragment(acc[mi][ni], 0.f);

    float4 areg[4];
    auto loadA = [&](int kc){
        int k0 = kc<<5;
        #pragma unroll
        for (int j=0; j<4; j++){
            int s = tid + j*256, r = s>>3, cq = s&7;
            int row = bm + r, col = k0 + cq*4;
            if (row < S_ && col+3 < S_)
                areg[j] = *reinterpret_cast<const float4*>(attn + (size_t)row*S_ + col);
            else if (row < S_){
                float t0 = (col   < S_) ? attn[(size_t)row*S_ + col  ] : -1e30f;
                float t1 = (col+1 < S_) ? attn[(size_t)row*S_ + col+1] : -1e30f;
                float t2 = (col+2 < S_) ? attn[(size_t)row*S_ + col+2] : -1e30f;
                float t3 = (col+3 < S_) ? attn[(size_t)row*S_ + col+3] : -1e30f;
                areg[j] = make_float4(t0,t1,t2,t3);
            } else areg[j] = make_float4(-1e30f,-1e30f,-1e30f,-1e30f);
        }
    };
    loadA(0);
    __syncthreads();

    for (int kc = 0; kc < KC; kc++){
        int buf = kc & 1;
        #pragma unroll
        for (int j=0; j<4; j++){
            int s = tid + j*256, r = s>>3, cq = s&7;
            float m = st[r].x, inv = st[r].y;
            bool rv = (bm + r) < S_;
            union { fp16 h[4]; uint2 u; } ph, pl;
            float* av = reinterpret_cast<float*>(&areg[j]);
            #pragma unroll
            for (int u=0; u<4; u++){
                float p = rv ? __expf(av[u] - m) * inv : 0.f;
                split2(p, ph.h[u], pl.h[u]);
            }
            *reinterpret_cast<uint2*>(&Ph[buf][r*40 + cq*4]) = ph.u;
            *reinterpret_cast<uint2*>(&Pl[buf][r*40 + cq*4]) = pl.u;
        }
        if (kc+1 < KC){
            loadA(kc+1);
            stage_tile<256>(vT, S_, 0, 64, (kc+1)<<5, S_, Vs[buf^1], tid, 64);
            CP_COMMIT();
            asm volatile("cp.async.wait_group 1;");
        } else {
            asm volatile("cp.async.wait_group 0;");
        }
        __syncthreads();
        #pragma unroll
        for (int ks=0; ks<2; ks++){
            wmma::fragment<wmma::matrix_b,16,16,16,fp16,wmma::col_major> b_f[2];
            #pragma unroll
            for (int ni=0; ni<2; ni++)
                wmma::load_matrix_sync(b_f[ni], Vs[buf] + (wcol+ni*16)*40 + ks*16, 40);
            #pragma unroll
            for (int mi=0; mi<2; mi++){
                wmma::fragment<wmma::matrix_a,16,16,16,fp16,wmma::row_major> ah_f, al_f;
                wmma::load_matrix_sync(ah_f, Ph[buf] + (wrow+mi*16)*40 + ks*16, 40);
                wmma::load_matrix_sync(al_f, Pl[buf] + (wrow+mi*16)*40 + ks*16, 40);
                #pragma unroll
                for (int ni=0; ni<2; ni++){
                    wmma::mma_sync(acc[mi][ni], ah_f, b_f[ni], acc[mi][ni]);
                    wmma::mma_sync(acc[mi][ni], al_f, b_f[ni], acc[mi][ni]);
                }
            }
        }
        __syncthreads();
    }

    float* eb = reinterpret_cast<float*>(Ph) + warp*320;
    #pragma unroll
    for (int mi=0; mi<2; mi++){
        #pragma unroll
        for (int ni=0; ni<2; ni++){
            wmma::store_matrix_sync(eb, acc[mi][ni], 20, wmma::mem_row_major);
            __syncwarp();
            int row0 = bm + wrow + mi*16, col0 = wcol + ni*16;
            #pragma unroll
            for (int j=0; j<8; j++){
                int e = lane + j*32, r = e>>4, c = e&15;
                int gr = row0 + r, gc = col0 + c;
                if (gr < S_){
                    size_t o = ((size_t)(g>>4)*S_ + gr)*1024 + (size_t)(g&15)*64 + gc;
                    fp16 h,l; split2(eb[r*20 + c], h, l);
                    oh[o]=h; ol[o]=l;
                }
            }
            __syncwarp();
        }
    }
}

__global__ void ln_k(const float* __restrict__ x, const float* __restrict__ w,
                     const float* __restrict__ bp, float* __restrict__ of,
                     fp16* __restrict__ oh, fp16* __restrict__ ol,
                     int Cw, float eps, int mode, const float* __restrict__ res)
{
    __shared__ float r1[8], r2[8], st[2];
    const int row = blockIdx.x, tid = threadIdx.x, lane = tid&31, wd = tid>>5;
    const float* xr = x + (size_t)row*Cw;
    float s=0.f, sq=0.f;
    for (int i = tid; i < Cw; i += 256){ float t = xr[i]; s += t; sq += t*t; }
    #pragma unroll
    for (int o=16;o;o>>=1){ s+=__shfl_down_sync(~0u,s,o); sq+=__shfl_down_sync(~0u,sq,o); }
    if (lane==0){ r1[wd]=s; r2[wd]=sq; }
    __syncthreads();
    if (tid==0){ float S=0,Q=0; for(int i=0;i<8;i++){S+=r1[i];Q+=r2[i];}
        float m=S/Cw, v=Q/Cw-m*m; st[0]=m; st[1]=rsqrtf(v+eps); }
    __syncthreads();
    float mean=st[0], rstd=st[1];
    for (int i = tid; i < Cw; i += 256){
        float y = (xr[i]-mean)*rstd*w[i] + bp[i];
        if (mode==2) of[(size_t)row*Cw+i] = y + res[(size_t)row*Cw+i];
        else { if (mode==1) y = gelu_f(y);
            fp16 h,l; split2(y,h,l); oh[(size_t)row*Cw+i]=h; ol[(size_t)row*Cw+i]=l; }
    }
}

__global__ void repack_k(const float* __restrict__ qkv,
    fp16* __restrict__ qh, fp16* __restrict__ ql, fp16* __restrict__ kh,
    fp16* __restrict__ vTh)
{
    __shared__ float sv[32][65];
    const int g = blockIdx.y, s0 = blockIdx.x*32, b = g>>4, n = g&15, t = threadIdx.x;
    for (int e = t; e < 2048; e += 256){
        int sl = e>>6, d = e&63, s = s0+sl;
        if (s < S_){
            size_t base = ((size_t)(b*S_+s))*3072 + n*64 + d;
            float qv = qkv[base]*0.125f;
            sv[sl][d] = qkv[base+2048];
            size_t o = ((size_t)g*S_+s)*64 + d;
            fp16 h,l; split2(qv,h,l); qh[o]=h; ql[o]=l;
            kh[o] = __float2half_rn(qkv[base+1024]);
        }
    }
    __syncthreads();
    for (int e = t; e < 2048; e += 256){
        int d = e>>5, j = e&31, s = s0+j;
        if (s < S_)
            vTh[((size_t)g*64+d)*S_ + s] = __float2half_rn(sv[j][d]);
    }
}

__global__ void relbias_k(const float* __restrict__ qkv, const float* __restrict__ rh,
                          const float* __restrict__ rw, float* __restrict__ bh, float* __restrict__ bw)
{
    const int s = blockIdx.x % S_, g = blockIdx.x / S_, b = g>>4, n = g&15;
    __shared__ float qs[64];
    const int t = threadIdx.x;
    qs[t] = qkv[((size_t)(b*S_+s))*3072 + n*64 + t];
    __syncthreads();
    const int h = s/28, w = s%28;
    if (t < 28){
        const float* r = rh + (size_t)(h-t+27)*64; float a=0.f;
        #pragma unroll
        for (int d=0;d<64;d++) a = fmaf(qs[d], r[d], a);
        bh[((size_t)g*S_+s)*28 + t] = a;
    } else if (t >= 32 && t < 60){
        const int l = t-32;
        const float* r = rw + (size_t)(w-l+27)*64; float a=0.f;
        #pragma unroll
        for (int d=0;d<64;d++) a = fmaf(qs[d], r[d], a);
        bw[((size_t)g*S_+s)*28 + l] = a;
    }
}

__global__ void wsplit_all(
    const float* s0, const float* s1, const float* s2, const float* s3,
    const float* s4, const float* s5, const float* s6,
    fp16* d0, fp16* d1, fp16* d2, fp16* d3, fp16* d4, fp16* d5, fp16* d6)
{
    int t = blockIdx.x;
    const float* src; fp16* dst; int K, N, loc;
    if      (t <  3072){ src=s0; dst=d0; K=C_;     N=3*C_;  loc=t; }
    else if (t <  4096){ src=s1; dst=d1; K=C_;     N=C_;    loc=t-3072; }
    else if (t <  8192){ src=s2; dst=d2; K=C_;     N=HID_;  loc=t-4096; }
    else if (t < 12288){ src=s3; dst=d3; K=HID_;   N=C_;    loc=t-8192; }
    else if (t < 12800){ src=s4; dst=d4; K=C_;     N=BC_;   loc=t-12288; }
    else if (t < 15104){ src=s5; dst=d5; K=9*BC_;  N=BC_;   loc=t-12800; }
    else               { src=s6; dst=d6; K=BC_;    N=C_;    loc=t-15104; }
    int kt = K >> 5;
    int k0 = (loc % kt) * 32, n0 = (loc / kt) * 32;

    __shared__ float s[32][33];
    const int tx = threadIdx.x, ty = threadIdx.y;
    #pragma unroll
    for (int y=0;y<32;y+=8) s[ty+y][tx] = src[(size_t)(k0+ty+y)*N + n0+tx];
    __syncthreads();
    #pragma unroll
    for (int y=0;y<32;y+=8)
        dst[(size_t)(n0+ty+y)*K + k0+tx] = __float2half_rn(s[tx][ty+y]);
}

constexpr int SM128 = (2*128*40 + 128*40)*2*2;   // 61440 B
constexpr int SM256 = (2*128*40 + 256*40)*2*2;   // 81920 B
#define GSA(p, sym) cudaGetSymbolAddress((void**)&p, sym)
extern "C" void kernel_launch(void* const* d_in, const int* in_sizes, int n_in,
                              void* d_out, int out_size)
{
    const float *x=(const float*)d_in[0], *n1w=(const float*)d_in[1], *n1b=(const float*)d_in[2],
        *qkvw=(const float*)d_in[3], *qkvb=(const float*)d_in[4], *pw=(const float*)d_in[5],
        *pb=(const float*)d_in[6], *relh=(const float*)d_in[7], *relw=(const float*)d_in[8],
        *n2w=(const float*)d_in[9], *n2b=(const float*)d_in[10], *f1w=(const float*)d_in[11],
        *f1b=(const float*)d_in[12], *f2w=(const float*)d_in[13], *f2b=(const float*)d_in[14],
        *c1w=(const float*)d_in[15], *l1w=(const float*)d_in[16], *l1b=(const float*)d_in[17],
        *c2w=(const float*)d_in[18], *l2w=(const float*)d_in[19], *l2b=(const float*)d_in[20],
        *c3w=(const float*)d_in[21], *l3w=(const float*)d_in[22], *l3b=(const float*)d_in[23];
    float* out = (float*)d_out;

    float *qkv,*bh,*bw,*attn,*x1,*x2,*c1,*c2,*c3;
    fp16 *xnh,*xnl,*qh,*ql,*kh,*vTh,*aoh,*aol,*mh,*ml,*x2h,*x2l,*c1h,*c1l,*c2h,*c2l;
    fp16 *wah,*wbh,*wch,*wdh,*weh,*wfh,*wgh;
    GSA(qkv,g_qkv); GSA(bh,g_bh); GSA(bw,g_bw); GSA(attn,g_attn); GSA(x1,g_x1); GSA(x2,g_x2);
    GSA(c1,g_c1); GSA(c2,g_c2); GSA(c3,g_c3);
    GSA(xnh,g_xnh); GSA(xnl,g_xnl); GSA(qh,g_qh); GSA(ql,g_ql); GSA(kh,g_kh);
    GSA(vTh,g_vTh); GSA(aoh,g_aoh); GSA(aol,g_aol);
    GSA(mh,g_mh); GSA(ml,g_ml); GSA(x2h,g_x2h); GSA(x2l,g_x2l);
    GSA(c1h,g_c1h); GSA(c1l,g_c1l); GSA(c2h,g_c2h); GSA(c2l,g_c2l);
    GSA(wah,g_wah); GSA(wbh,g_wbh); GSA(wch,g_wch); GSA(wdh,g_wdh);
    GSA(weh,g_weh); GSA(wfh,g_wfh); GSA(wgh,g_wgh);

    cudaFuncSetAttribute(mma_gemm<256,0,0,512>, cudaFuncAttributeMaxDynamicSharedMemorySize, SM256);
    cudaFuncSetAttribute(mma_gemm<256,1,0,512>, cudaFuncAttributeMaxDynamicSharedMemorySize, SM256);
    cudaFuncSetAttribute(mma_gemm<256,2,0,512>, cudaFuncAttributeMaxDynamicSharedMemorySize, SM256);
    cudaFuncSetAttribute(mma_gemm<256,5,0,512>, cudaFuncAttributeMaxDynamicSharedMemorySize, SM256);
    cudaFuncSetAttribute(mma_gemm<128,3,0,256>, cudaFuncAttributeMaxDynamicSharedMemorySize, SM128);
    cudaFuncSetAttribute(mma_gemm<128,0,0,256>, cudaFuncAttributeMaxDynamicSharedMemorySize, SM128);
    cudaFuncSetAttribute(mma_gemm<128,0,1,256>, cudaFuncAttributeMaxDynamicSharedMemorySize, SM128);

    wsplit_all<<<15616, dim3(32,8)>>>(qkvw, pw, f1w, f2w, c1w, c2w, c3w,
                                      wah, wbh, wch, wdh, weh, wfh, wgh);

    ln_k<<<M_,256>>>(x, n1w, n1b, nullptr, xnh, xnl, C_, 1e-5f, 0, nullptr);
    mma_gemm<256,0,0,512><<<dim3(49,12,1),512,SM256>>>(xnh,xnl,wah, qkv,nullptr,nullptr,
        M_,3*C_,C_, C_,C_,3*C_, 0,0,0, qkvb,nullptr,0,nullptr,nullptr);
    repack_k<<<dim3(25,G_),256>>>(qkv,qh,ql,kh,vTh);
    relbias_k<<<G_*S_,64>>>(qkv,relh,relw,bh,bw);
    mma_gemm<128,3,0,256><<<dim3(7,7,G_),256,SM128>>>(qh,ql,kh, attn,nullptr,nullptr,
        S_,S_,64, 64,64,S_, (long long)S_*64,(long long)S_*64,(long long)S_*S_,
        nullptr,nullptr,0,bh,bw);
    av_k<<<dim3(7,G_),256>>>(attn, vTh, aoh, aol);
    mma_gemm<256,2,0,512><<<dim3(49,4,1),512,SM256>>>(aoh,aol,wbh, x1,nullptr,nullptr,
        M_,C_,C_, C_,C_,C_, 0,0,0, pb,x,C_,nullptr,nullptr);
    ln_k<<<M_,256>>>(x1, n2w, n2b, nullptr, xnh, xnl, C_, 1e-5f, 0, nullptr);
    mma_gemm<256,1,0,512><<<dim3(49,16,1),512,SM256>>>(xnh,xnl,wch, nullptr,mh,ml,
        M_,HID_,C_, C_,C_,HID_, 0,0,0, f1b,nullptr,0,nullptr,nullptr);
    mma_gemm<256,5,0,512><<<dim3(49,4,1),512,SM256>>>(mh,ml,wdh, x2,x2h,x2l,
        M_,C_,HID_, HID_,HID_,C_, 0,0,0, f2b,x1,C_,nullptr,nullptr);
    mma_gemm<128,0,0,256><<<dim3(49,4,1),256,SM128>>>(x2h,x2l,weh, c1,nullptr,nullptr,
        M_,BC_,C_, C_,C_,BC_, 0,0,0, nullptr,nullptr,0,nullptr,nullptr);
    ln_k<<<M_,256>>>(c1, l1w, l1b, nullptr, c1h, c1l, BC_, 1e-6f, 1, nullptr);
    mma_gemm<128,0,1,256><<<dim3(49,4,1),256,SM128>>>(c1h,c1l,wfh, c2,nullptr,nullptr,
        M_,BC_,9*BC_, 0,9*BC_,BC_, 0,0,0, nullptr,nullptr,0,nullptr,nullptr);
    ln_k<<<M_,256>>>(c2, l2w, l2b, nullptr, c2h, c2l, BC_, 1e-6f, 1, nullptr);
    mma_gemm<256,0,0,512><<<dim3(49,4,1),512,SM256>>>(c2h,c2l,wgh, c3,nullptr,nullptr,
        M_,C_,BC_, BC_,BC_,C_, 0,0,0, nullptr,nullptr,0,nullptr,nullptr);
    ln_k<<<M_,256>>>(c3, l3w, l3b, out, nullptr, nullptr, C_, 1e-6f, 2, x2);
}

// round 16
// speedup vs baseline: 1.0337x; 1.0179x over previous
#include <cuda_runtime.h>
#include <cuda_fp16.h>
#include <mma.h>
#include <math.h>
#include <stdint.h>

using namespace nvcuda;
typedef __half fp16;
constexpr int C_=1024, S_=784, M_=6272, HID_=4096, BC_=512, G_=128;

__device__ __align__(16) fp16 g_xnh[M_*C_], g_xnl[M_*C_];
__device__ __align__(16) float g_v32[M_*C_];
__device__ __align__(16) fp16 g_qh[G_*S_*64], g_ql[G_*S_*64], g_kh[G_*S_*64];
__device__ __align__(16) fp16 g_vTh[G_*64*S_];
__device__ __align__(16) float g_bh[G_*S_*28], g_bw[G_*S_*28];
__device__ __align__(16) float g_attn[(size_t)G_*S_*S_];
__device__ __align__(16) fp16 g_aoh[M_*C_], g_aol[M_*C_];
__device__ __align__(16) float g_x1[M_*C_];
__device__ __align__(16) fp16 g_mh[M_*HID_], g_ml[M_*HID_];
__device__ __align__(16) float g_x2[M_*C_];
__device__ __align__(16) fp16 g_x2h[M_*C_], g_x2l[M_*C_];
__device__ __align__(16) float g_c1[M_*BC_];
__device__ __align__(16) fp16 g_c1h[M_*BC_], g_c1l[M_*BC_];
__device__ __align__(16) float g_c2[M_*BC_];
__device__ __align__(16) fp16 g_c2h[M_*BC_], g_c2l[M_*BC_];
__device__ __align__(16) float g_c3[M_*C_];
__device__ __align__(16) fp16 g_wah[3*C_*C_];
__device__ __align__(16) fp16 g_wbh[C_*C_];
__device__ __align__(16) fp16 g_wch[HID_*C_];
__device__ __align__(16) fp16 g_wdh[C_*HID_];
__device__ __align__(16) fp16 g_weh[BC_*C_];
__device__ __align__(16) fp16 g_wfh[BC_*9*BC_];
__device__ __align__(16) fp16 g_wgh[C_*BC_];

__device__ __forceinline__ float gelu_f(float x){ return 0.5f*x*(1.0f+erff(x*0.7071067811865475f)); }
__device__ __forceinline__ void split2(float x, fp16&h, fp16&l){
    h = __float2half_rn(x); l = __float2half_rn(x - __half2float(h));
}

__device__ __forceinline__ void cp16(fp16* sm, const fp16* gm, bool pred){
    uint32_t sa = (uint32_t)__cvta_generic_to_shared(sm);
    int sz = pred ? 16 : 0;
    asm volatile("cp.async.ca.shared.global [%0], [%1], 16, %2;" :: "r"(sa), "l"(gm), "r"(sz));
}
#define CP_COMMIT() asm volatile("cp.async.commit_group;")

__device__ __forceinline__ void stage_tile(const fp16* __restrict__ src, int ld,
        int row0, int rmax, int k0, int K, fp16* sm, int tid, int rows){
    for (int i = tid; i < rows*4; i += 256){
        int r = i>>2, cq = i&3;
        int gr = row0 + r, gk = k0 + (cq<<3);
        bool p = (gr < rmax && gk < K);
        cp16(sm + r*40 + (cq<<3), p ? src + (size_t)gr*ld + gk : src, p);
    }
}
__device__ __forceinline__ void stage_conv(const fp16* __restrict__ src, int row0, int k0,
        fp16* sm, int tid){
    int ky = k0/1536, kxr = k0 - ky*1536, kx = kxr>>9, ci0 = kxr&511;
    for (int i = tid; i < 512; i += 256){
        int r = i>>2, cq = i&3;
        int gr = row0 + r;
        bool p = false; const fp16* g = src;
        if (gr < M_){
            int b = gr/S_, rem = gr - b*S_, h = rem/28, w = rem - h*28;
            int ih = h+ky-1, iw = w+kx-1;
            if ((unsigned)ih<28u && (unsigned)iw<28u){
                p = true; g = src + ((size_t)((b*28+ih)*28+iw))*BC_ + ci0 + (cq<<3);
            }
        }
        cp16(sm + r*40 + (cq<<3), g, p);
    }
}

// fp16x2 wmma GEMM: D = (Ah+Al)@Bh^T, 2-stage cp.async pipeline. B given as [N,K].
// EPI 0: fp32(+bias)  1: gelu->split  2: +bias+res->fp32  3: +bh+bw->fp32
// EPI 5: +bias+res->fp32 AND split
// EPI 6 (qkv): col<1024 -> split(v*0.125) to qh/ql; <2048 -> kh fp16; else v fp32
template<int BN, int EPI, int GATHER>
__global__ void __launch_bounds__(256) mma_gemm(
    const fp16* __restrict__ Ah, const fp16* __restrict__ Al,
    const fp16* __restrict__ Bh,
    float* __restrict__ o0, fp16* __restrict__ o1, fp16* __restrict__ o2,
    fp16* __restrict__ o3,
    int M, int N, int K, int lda, int ldb, int ldc,
    long long sA, long long sB, long long sC,
    const float* __restrict__ bias, const float* __restrict__ res, int ldres,
    const float* __restrict__ bhp, const float* __restrict__ bwp)
{
    constexpr int BM = 128;
    constexpr int WarpsN = 4, WarpsM = 2;
    constexpr int WM = BM/WarpsM, WN = BN/WarpsN;
    constexpr int MI = WM/16, NI = WN/16;
    constexpr int ATILE = BM*40, BTILE = BN*40;
    constexpr int STAGE = 2*ATILE + BTILE;
    extern __shared__ __align__(128) fp16 pool[];

    const int tid = threadIdx.x, warp = tid>>5, lane = tid&31;
    const int bm = blockIdx.x*BM, bn = blockIdx.y*BN, g = blockIdx.z;
    Ah += (size_t)g*sA; Al += (size_t)g*sA; Bh += (size_t)g*sB;
    const int wrow = (warp/WarpsN)*WM, wcol = (warp%WarpsN)*WN;

    wmma::fragment<wmma::accumulator,16,16,16,float> acc[MI][NI];
    #pragma unroll
    for (int mi=0; mi<MI; mi++)
        #pragma unroll
        for (int ni=0; ni<NI; ni++) wmma::fill_fragment(acc[mi][ni], 0.f);

    const int KC = (K+31)>>5;
    auto issue = [&](int kc, int s){
        fp16* st = pool + s*STAGE;
        int k0 = kc<<5;
        if (GATHER){ stage_conv(Ah, bm, k0, st, tid); stage_conv(Al, bm, k0, st+ATILE, tid); }
        else { stage_tile(Ah, lda, bm, M, k0, K, st, tid, BM);
               stage_tile(Al, lda, bm, M, k0, K, st+ATILE, tid, BM); }
        stage_tile(Bh, ldb, bn, N, k0, K, st+2*ATILE, tid, BN);
        CP_COMMIT();
    };
    issue(0, 0);
    for (int kc = 0; kc < KC; kc++){
        int buf = kc & 1;
        if (kc+1 < KC){
            issue(kc+1, buf^1);
            asm volatile("cp.async.wait_group 1;");
        } else {
            asm volatile("cp.async.wait_group 0;");
        }
        __syncthreads();
        fp16 *Ash = pool + buf*STAGE, *Asl = Ash + ATILE, *Bsh = Ash + 2*ATILE;
        #pragma unroll
        for (int ks=0; ks<2; ks++){
            wmma::fragment<wmma::matrix_b,16,16,16,fp16,wmma::col_major> bh_f[NI];
            #pragma unroll
            for (int ni=0; ni<NI; ni++)
                wmma::load_matrix_sync(bh_f[ni], Bsh + (wcol+ni*16)*40 + ks*16, 40);
            #pragma unroll
            for (int mi=0; mi<MI; mi++){
                wmma::fragment<wmma::matrix_a,16,16,16,fp16,wmma::row_major> ah_f, al_f;
                wmma::load_matrix_sync(ah_f, Ash + (wrow+mi*16)*40 + ks*16, 40);
                wmma::load_matrix_sync(al_f, Asl + (wrow+mi*16)*40 + ks*16, 40);
                #pragma unroll
                for (int ni=0; ni<NI; ni++){
                    wmma::mma_sync(acc[mi][ni], ah_f, bh_f[ni], acc[mi][ni]);
                    wmma::mma_sync(acc[mi][ni], al_f, bh_f[ni], acc[mi][ni]);
                }
            }
        }
        __syncthreads();
    }

    float* eb = reinterpret_cast<float*>(pool) + warp*320;   // 16x20
    #pragma unroll
    for (int mi=0; mi<MI; mi++){
        #pragma unroll
        for (int ni=0; ni<NI; ni++){
            wmma::store_matrix_sync(eb, acc[mi][ni], 20, wmma::mem_row_major);
            __syncwarp();
            int row0 = bm + wrow + mi*16, col0 = bn + wcol + ni*16;
            #pragma unroll
            for (int j=0; j<8; j++){
                int e = lane + j*32, r = e>>4, c = e&15;
                int gr = row0 + r, gc = col0 + c;
                if (gr < M && gc < N){
                    float v = eb[r*20 + c];
                    if (bias) v += bias[gc];
                    if (EPI == 1){ v = gelu_f(v); fp16 h,l; split2(v,h,l);
                        o1[(size_t)gr*ldc+gc]=h; o2[(size_t)gr*ldc+gc]=l; }
                    else if (EPI == 2){ o0[(size_t)gr*ldc+gc] = v + res[(size_t)gr*ldres+gc]; }
                    else if (EPI == 3){
                        v += bhp[((size_t)g*S_+gr)*28 + gc/28] + bwp[((size_t)g*S_+gr)*28 + gc%28];
                        o0[(size_t)g*sC + (size_t)gr*ldc + gc] = v; }
                    else if (EPI == 5){ v += res[(size_t)gr*ldres+gc];
                        o0[(size_t)gr*ldc+gc] = v; fp16 h,l; split2(v,h,l);
                        o1[(size_t)gr*ldc+gc]=h; o2[(size_t)gr*ldc+gc]=l; }
                    else if (EPI == 6){
                        int sec = gc >> 10, cc = gc & 1023;
                        int n = cc >> 6, d = cc & 63;
                        int b = gr / S_, s = gr - b*S_;
                        size_t o = ((size_t)((b<<4)+n)*S_ + s)*64 + d;
                        if (sec == 0){ fp16 h,l; split2(v*0.125f,h,l); o1[o]=h; o2[o]=l; }
                        else if (sec == 1){ o3[o] = __float2half_rn(v); }
                        else { o0[(size_t)gr*1024 + cc] = v; }
                    }
                    else o0[(size_t)gr*ldc+gc] = v;
                }
            }
            __syncwarp();
        }
    }
}

// fused stats + softmax + AV: O[g] = softmax(attn[g]) @ V[g]^T, scatter split
__global__ void __launch_bounds__(256) av_k(
    const float* __restrict__ attn,
    const fp16* __restrict__ vT, fp16* __restrict__ oh, fp16* __restrict__ ol)
{
    constexpr int KC = 25;
    __shared__ __align__(16) fp16 Ph[2][128*40], Pl[2][128*40], Vs[2][64*40];
    __shared__ float2 st[128];
    const int tid = threadIdx.x, warp = tid>>5, lane = tid&31;
    const int bm = blockIdx.x*128, g = blockIdx.y;
    attn += (size_t)g*S_*S_;
    vT   += (size_t)g*64*S_;
    const int wrow = (warp>>1)*32, wcol = (warp&1)*32;

    stage_tile(vT, S_, 0, 64, 0, S_, Vs[0], tid, 64);
    CP_COMMIT();

    for (int rr = 0; rr < 16; rr++){
        int r = warp*16 + rr;
        int grow = bm + r;
        float vbuf[25];
        float m = -1e30f;
        if (grow < S_){
            const float* p = attn + (size_t)grow*S_;
            #pragma unroll
            for (int i=0;i<25;i++){
                int col = lane + i*32;
                vbuf[i] = (col < S_) ? p[col] : -1e30f;
                m = fmaxf(m, vbuf[i]);
            }
        } else {
            #pragma unroll
            for (int i=0;i<25;i++) vbuf[i] = -1e30f;
        }
        #pragma unroll
        for (int o=16;o;o>>=1) m = fmaxf(m, __shfl_xor_sync(~0u, m, o));
        float s = 0.f;
        if (grow < S_){
            #pragma unroll
            for (int i=0;i<25;i++){
                int col = lane + i*32;
                if (col < S_) s += __expf(vbuf[i] - m);
            }
        }
        #pragma unroll
        for (int o=16;o;o>>=1) s += __shfl_xor_sync(~0u, s, o);
        if (lane == 0)
            st[r] = (grow < S_) ? make_float2(m, 1.f/s) : make_float2(0.f, 0.f);
    }

    wmma::fragment<wmma::accumulator,16,16,16,float> acc[2][2];
    #pragma unroll
    for (int mi=0; mi<2; mi++)
        #pragma unroll
        for (int ni=0; ni<2; ni++) wmma::fill_fragment(acc[mi][ni], 0.f);

    float4 areg[4];
    auto loadA = [&](int kc){
        int k0 = kc<<5;
        #pragma unroll
        for (int j=0; j<4; j++){
            int s = tid + j*256, r = s>>3, cq = s&7;
            int row = bm + r, col = k0 + cq*4;
            if (row < S_ && col+3 < S_)
                areg[j] = *reinterpret_cast<const float4*>(attn + (size_t)row*S_ + col);
            else if (row < S_){
                float t0 = (col   < S_) ? attn[(size_t)row*S_ + col  ] : -1e30f;
                float t1 = (col+1 < S_) ? attn[(size_t)row*S_ + col+1] : -1e30f;
                float t2 = (col+2 < S_) ? attn[(size_t)row*S_ + col+2] : -1e30f;
                float t3 = (col+3 < S_) ? attn[(size_t)row*S_ + col+3] : -1e30f;
                areg[j] = make_float4(t0,t1,t2,t3);
            } else areg[j] = make_float4(-1e30f,-1e30f,-1e30f,-1e30f);
        }
    };
    loadA(0);
    __syncthreads();

    for (int kc = 0; kc < KC; kc++){
        int buf = kc & 1;
        #pragma unroll
        for (int j=0; j<4; j++){
            int s = tid + j*256, r = s>>3, cq = s&7;
            float m = st[r].x, inv = st[r].y;
            bool rv = (bm + r) < S_;
            union { fp16 h[4]; uint2 u; } ph, pl;
            float* av = reinterpret_cast<float*>(&areg[j]);
            #pragma unroll
            for (int u=0; u<4; u++){
                float p = rv ? __expf(av[u] - m) * inv : 0.f;
                split2(p, ph.h[u], pl.h[u]);
            }
            *reinterpret_cast<uint2*>(&Ph[buf][r*40 + cq*4]) = ph.u;
            *reinterpret_cast<uint2*>(&Pl[buf][r*40 + cq*4]) = pl.u;
        }
        if (kc+1 < KC){
            loadA(kc+1);
            stage_tile(vT, S_, 0, 64, (kc+1)<<5, S_, Vs[buf^1], tid, 64);
            CP_COMMIT();
            asm volatile("cp.async.wait_group 1;");
        } else {
            asm volatile("cp.async.wait_group 0;");
        }
        __syncthreads();
        #pragma unroll
        for (int ks=0; ks<2; ks++){
            wmma::fragment<wmma::matrix_b,16,16,16,fp16,wmma::col_major> b_f[2];
            #pragma unroll
            for (int ni=0; ni<2; ni++)
                wmma::load_matrix_sync(b_f[ni], Vs[buf] + (wcol+ni*16)*40 + ks*16, 40);
            #pragma unroll
            for (int mi=0; mi<2; mi++){
                wmma::fragment<wmma::matrix_a,16,16,16,fp16,wmma::row_major> ah_f, al_f;
                wmma::load_matrix_sync(ah_f, Ph[buf] + (wrow+mi*16)*40 + ks*16, 40);
                wmma::load_matrix_sync(al_f, Pl[buf] + (wrow+mi*16)*40 + ks*16, 40);
                #pragma unroll
                for (int ni=0; ni<2; ni++){
                    wmma::mma_sync(acc[mi][ni], ah_f, b_f[ni], acc[mi][ni]);
                    wmma::mma_sync(acc[mi][ni], al_f, b_f[ni], acc[mi][ni]);
                }
            }
        }
        __syncthreads();
    }

    float* eb = reinterpret_cast<float*>(Ph) + warp*320;
    #pragma unroll
    for (int mi=0; mi<2; mi++){
        #pragma unroll
        for (int ni=0; ni<2; ni++){
            wmma::store_matrix_sync(eb, acc[mi][ni], 20, wmma::mem_row_major);
            __syncwarp();
            int row0 = bm + wrow + mi*16, col0 = wcol + ni*16;
            #pragma unroll
            for (int j=0; j<8; j++){
                int e = lane + j*32, r = e>>4, c = e&15;
                int gr = row0 + r, gc = col0 + c;
                if (gr < S_){
                    size_t o = ((size_t)(g>>4)*S_ + gr)*1024 + (size_t)(g&15)*64 + gc;
                    fp16 h,l; split2(eb[r*20 + c], h, l);
                    oh[o]=h; ol[o]=l;
                }
            }
            __syncwarp();
        }
    }
}

__global__ void ln_k(const float* __restrict__ x, const float* __restrict__ w,
                     const float* __restrict__ bp, float* __restrict__ of,
                     fp16* __restrict__ oh, fp16* __restrict__ ol,
                     int Cw, float eps, int mode, const float* __restrict__ res)
{
    __shared__ float r1[8], r2[8], st[2];
    const int row = blockIdx.x, tid = threadIdx.x, lane = tid&31, wd = tid>>5;
    const float* xr = x + (size_t)row*Cw;
    float s=0.f, sq=0.f;
    for (int i = tid; i < Cw; i += 256){ float t = xr[i]; s += t; sq += t*t; }
    #pragma unroll
    for (int o=16;o;o>>=1){ s+=__shfl_down_sync(~0u,s,o); sq+=__shfl_down_sync(~0u,sq,o); }
    if (lane==0){ r1[wd]=s; r2[wd]=sq; }
    __syncthreads();
    if (tid==0){ float S=0,Q=0; for(int i=0;i<8;i++){S+=r1[i];Q+=r2[i];}
        float m=S/Cw, v=Q/Cw-m*m; st[0]=m; st[1]=rsqrtf(v+eps); }
    __syncthreads();
    float mean=st[0], rstd=st[1];
    for (int i = tid; i < Cw; i += 256){
        float y = (xr[i]-mean)*rstd*w[i] + bp[i];
        if (mode==2) of[(size_t)row*Cw+i] = y + res[(size_t)row*Cw+i];
        else { if (mode==1) y = gelu_f(y);
            fp16 h,l; split2(y,h,l); oh[(size_t)row*Cw+i]=h; ol[(size_t)row*Cw+i]=l; }
    }
}

// v32 [B,S,NH*HD] -> vTh [g,d,s]   (g = b*16+n)
__global__ void repack_v(const float* __restrict__ v32, fp16* __restrict__ vTh)
{
    __shared__ float sv[32][65];
    const int g = blockIdx.y, s0 = blockIdx.x*32, b = g>>4, n = g&15, t = threadIdx.x;
    for (int e = t; e < 2048; e += 256){
        int sl = e>>6, d = e&63, s = s0+sl;
        if (s < S_)
            sv[sl][d] = v32[((size_t)(b*S_ + s))*1024 + n*64 + d];
    }
    __syncthreads();
    for (int e = t; e < 2048; e += 256){
        int d = e>>5, j = e&31, s = s0+j;
        if (s < S_)
            vTh[((size_t)g*64+d)*S_ + s] = __float2half_rn(sv[j][d]);
    }
}

// rel-pos bias from split q (q stored scaled by 0.125 -> multiply dots by 8)
__global__ void relbias_k(const fp16* __restrict__ qh, const fp16* __restrict__ ql,
                          const float* __restrict__ rh, const float* __restrict__ rw,
                          float* __restrict__ bh, float* __restrict__ bw)
{
    const int s = blockIdx.x % S_, g = blockIdx.x / S_;
    __shared__ float qs[64];
    const int t = threadIdx.x;
    size_t qo = ((size_t)g*S_ + s)*64 + t;
    qs[t] = (__half2float(qh[qo]) + __half2float(ql[qo])) * 8.0f;
    __syncthreads();
    const int h = s/28, w = s%28;
    if (t < 28){
        const float* r = rh + (size_t)(h-t+27)*64; float a=0.f;
        #pragma unroll
        for (int d=0;d<64;d++) a = fmaf(qs[d], r[d], a);
        bh[((size_t)g*S_+s)*28 + t] = a;
    } else if (t >= 32 && t < 60){
        const int l = t-32;
        const float* r = rw + (size_t)(w-l+27)*64; float a=0.f;
        #pragma unroll
        for (int d=0;d<64;d++) a = fmaf(qs[d], r[d], a);
        bw[((size_t)g*S_+s)*28 + l] = a;
    }
}

__global__ void wsplit_all(
    const float* s0, const float* s1, const float* s2, const float* s3,
    const float* s4, const float* s5, const float* s6,
    fp16* d0, fp16* d1, fp16* d2, fp16* d3, fp16* d4, fp16* d5, fp16* d6)
{
    int t = blockIdx.x;
    const float* src; fp16* dst; int K, N, loc;
    if      (t <  3072){ src=s0; dst=d0; K=C_;     N=3*C_;  loc=t; }
    else if (t <  4096){ src=s1; dst=d1; K=C_;     N=C_;    loc=t-3072; }
    else if (t <  8192){ src=s2; dst=d2; K=C_;     N=HID_;  loc=t-4096; }
    else if (t < 12288){ src=s3; dst=d3; K=HID_;   N=C_;    loc=t-8192; }
    else if (t < 12800){ src=s4; dst=d4; K=C_;     N=BC_;   loc=t-12288; }
    else if (t < 15104){ src=s5; dst=d5; K=9*BC_;  N=BC_;   loc=t-12800; }
    else               { src=s6; dst=d6; K=BC_;    N=C_;    loc=t-15104; }
    int kt = K >> 5;
    int k0 = (loc % kt) * 32, n0 = (loc / kt) * 32;

    __shared__ float s[32][33];
    const int tx = threadIdx.x, ty = threadIdx.y;
    #pragma unroll
    for (int y=0;y<32;y+=8) s[ty+y][tx] = src[(size_t)(k0+ty+y)*N + n0+tx];
    __syncthreads();
    #pragma unroll
    for (int y=0;y<32;y+=8)
        dst[(size_t)(n0+ty+y)*K + k0+tx] = __float2half_rn(s[tx][ty+y]);
}

constexpr int SM128 = (2*128*40 + 128*40)*2*2;   // 61440 B
#define GSA(p, sym) cudaGetSymbolAddress((void**)&p, sym)
extern "C" void kernel_launch(void* const* d_in, const int* in_sizes, int n_in,
                              void* d_out, int out_size)
{
    const float *x=(const float*)d_in[0], *n1w=(const float*)d_in[1], *n1b=(const float*)d_in[2],
        *qkvw=(const float*)d_in[3], *qkvb=(const float*)d_in[4], *pw=(const float*)d_in[5],
        *pb=(const float*)d_in[6], *relh=(const float*)d_in[7], *relw=(const float*)d_in[8],
        *n2w=(const float*)d_in[9], *n2b=(const float*)d_in[10], *f1w=(const float*)d_in[11],
        *f1b=(const float*)d_in[12], *f2w=(const float*)d_in[13], *f2b=(const float*)d_in[14],
        *c1w=(const float*)d_in[15], *l1w=(const float*)d_in[16], *l1b=(const float*)d_in[17],
        *c2w=(const float*)d_in[18], *l2w=(const float*)d_in[19], *l2b=(const float*)d_in[20],
        *c3w=(const float*)d_in[21], *l3w=(const float*)d_in[22], *l3b=(const float*)d_in[23];
    float* out = (float*)d_out;

    float *v32,*bh,*bw,*attn,*x1,*x2,*c1,*c2,*c3;
    fp16 *xnh,*xnl,*qh,*ql,*kh,*vTh,*aoh,*aol,*mh,*ml,*x2h,*x2l,*c1h,*c1l,*c2h,*c2l;
    fp16 *wah,*wbh,*wch,*wdh,*weh,*wfh,*wgh;
    GSA(v32,g_v32); GSA(bh,g_bh); GSA(bw,g_bw); GSA(attn,g_attn); GSA(x1,g_x1); GSA(x2,g_x2);
    GSA(c1,g_c1); GSA(c2,g_c2); GSA(c3,g_c3);
    GSA(xnh,g_xnh); GSA(xnl,g_xnl); GSA(qh,g_qh); GSA(ql,g_ql); GSA(kh,g_kh);
    GSA(vTh,g_vTh); GSA(aoh,g_aoh); GSA(aol,g_aol);
    GSA(mh,g_mh); GSA(ml,g_ml); GSA(x2h,g_x2h); GSA(x2l,g_x2l);
    GSA(c1h,g_c1h); GSA(c1l,g_c1l); GSA(c2h,g_c2h); GSA(c2l,g_c2l);
    GSA(wah,g_wah); GSA(wbh,g_wbh); GSA(wch,g_wch); GSA(wdh,g_wdh);
    GSA(weh,g_weh); GSA(wfh,g_wfh); GSA(wgh,g_wgh);

    cudaFuncSetAttribute(mma_gemm<128,0,0>, cudaFuncAttributeMaxDynamicSharedMemorySize, SM128);
    cudaFuncSetAttribute(mma_gemm<128,1,0>, cudaFuncAttributeMaxDynamicSharedMemorySize, SM128);
    cudaFuncSetAttribute(mma_gemm<128,2,0>, cudaFuncAttributeMaxDynamicSharedMemorySize, SM128);
    cudaFuncSetAttribute(mma_gemm<128,3,0>, cudaFuncAttributeMaxDynamicSharedMemorySize, SM128);
    cudaFuncSetAttribute(mma_gemm<128,5,0>, cudaFuncAttributeMaxDynamicSharedMemorySize, SM128);
    cudaFuncSetAttribute(mma_gemm<128,6,0>, cudaFuncAttributeMaxDynamicSharedMemorySize, SM128);
    cudaFuncSetAttribute(mma_gemm<128,0,1>, cudaFuncAttributeMaxDynamicSharedMemorySize, SM128);

    wsplit_all<<<15616, dim3(32,8)>>>(qkvw, pw, f1w, f2w, c1w, c2w, c3w,
                                      wah, wbh, wch, wdh, weh, wfh, wgh);

    ln_k<<<M_,256>>>(x, n1w, n1b, nullptr, xnh, xnl, C_, 1e-5f, 0, nullptr);
    mma_gemm<128,6,0><<<dim3(49,24,1),256,SM128>>>(xnh,xnl,wah, v32,qh,ql,kh,
        M_,3*C_,C_, C_,C_,3*C_, 0,0,0, qkvb,nullptr,0,nullptr,nullptr);
    repack_v<<<dim3(25,G_),256>>>(v32, vTh);
    relbias_k<<<G_*S_,64>>>(qh,ql,relh,relw,bh,bw);
    mma_gemm<128,3,0><<<dim3(7,7,G_),256,SM128>>>(qh,ql,kh, attn,nullptr,nullptr,nullptr,
        S_,S_,64, 64,64,S_, (long long)S_*64,(long long)S_*64,(long long)S_*S_,
        nullptr,nullptr,0,bh,bw);
    av_k<<<dim3(7,G_),256>>>(attn, vTh, aoh, aol);
    mma_gemm<128,2,0><<<dim3(49,8,1),256,SM128>>>(aoh,aol,wbh, x1,nullptr,nullptr,nullptr,
        M_,C_,C_, C_,C_,C_, 0,0,0, pb,x,C_,nullptr,nullptr);
    ln_k<<<M_,256>>>(x1, n2w, n2b, nullptr, xnh, xnl, C_, 1e-5f, 0, nullptr);
    mma_gemm<128,1,0><<<dim3(49,32,1),256,SM128>>>(xnh,xnl,wch, nullptr,mh,ml,nullptr,
        M_,HID_,C_, C_,C_,HID_, 0,0,0, f1b,nullptr,0,nullptr,nullptr);
    mma_gemm<128,5,0><<<dim3(49,8,1),256,SM128>>>(mh,ml,wdh, x2,x2h,x2l,nullptr,
        M_,C_,HID_, HID_,HID_,C_, 0,0,0, f2b,x1,C_,nullptr,nullptr);
    mma_gemm<128,0,0><<<dim3(49,4,1),256,SM128>>>(x2h,x2l,weh, c1,nullptr,nullptr,nullptr,
        M_,BC_,C_, C_,C_,BC_, 0,0,0, nullptr,nullptr,0,nullptr,nullptr);
    ln_k<<<M_,256>>>(c1, l1w, l1b, nullptr, c1h, c1l, BC_, 1e-6f, 1, nullptr);
    mma_gemm<128,0,1><<<dim3(49,4,1),256,SM128>>>(c1h,c1l,wfh, c2,nullptr,nullptr,nullptr,
        M_,BC_,9*BC_, 0,9*BC_,BC_, 0,0,0, nullptr,nullptr,0,nullptr,nullptr);
    ln_k<<<M_,256>>>(c2, l2w, l2b, nullptr, c2h, c2l, BC_, 1e-6f, 1, nullptr);
    mma_gemm<128,0,0><<<dim3(49,8,1),256,SM128>>>(c2h,c2l,wgh, c3,nullptr,nullptr,nullptr,
        M_,C_,BC_, BC_,BC_,C_, 0,0,0, nullptr,nullptr,0,nullptr,nullptr);
    ln_k<<<M_,256>>>(c3, l3w, l3b, out, nullptr, nullptr, C_, 1e-6f, 2, x2);
}

// round 17
// speedup vs baseline: 1.0457x; 1.0116x over previous
#include <cuda_runtime.h>
#include <cuda_fp16.h>
#include <mma.h>
#include <math.h>
#include <stdint.h>

using namespace nvcuda;
typedef __half fp16;
constexpr int C_=1024, S_=784, M_=6272, HID_=4096, BC_=512, G_=128;

__device__ __align__(16) fp16 g_xnh[M_*C_], g_xnl[M_*C_];
__device__ __align__(16) float g_v32[M_*C_];
__device__ __align__(16) fp16 g_qh[G_*S_*64], g_ql[G_*S_*64], g_kh[G_*S_*64];
__device__ __align__(16) fp16 g_vTh[G_*64*S_];
__device__ __align__(16) float g_bh[G_*S_*28], g_bw[G_*S_*28];
__device__ __align__(16) fp16 g_attn[(size_t)G_*S_*S_];
__device__ __align__(16) fp16 g_aoh[M_*C_], g_aol[M_*C_];
__device__ __align__(16) float g_x1[M_*C_];
__device__ __align__(16) fp16 g_mh[M_*HID_], g_ml[M_*HID_];
__device__ __align__(16) float g_x2[M_*C_];
__device__ __align__(16) fp16 g_x2h[M_*C_], g_x2l[M_*C_];
__device__ __align__(16) float g_c1[M_*BC_];
__device__ __align__(16) fp16 g_c1h[M_*BC_], g_c1l[M_*BC_];
__device__ __align__(16) float g_c2[M_*BC_];
__device__ __align__(16) fp16 g_c2h[M_*BC_], g_c2l[M_*BC_];
__device__ __align__(16) float g_c3[M_*C_];
__device__ __align__(16) fp16 g_wah[3*C_*C_];
__device__ __align__(16) fp16 g_wbh[C_*C_];
__device__ __align__(16) fp16 g_wch[HID_*C_];
__device__ __align__(16) fp16 g_wdh[C_*HID_];
__device__ __align__(16) fp16 g_weh[BC_*C_];
__device__ __align__(16) fp16 g_wfh[BC_*9*BC_];
__device__ __align__(16) fp16 g_wgh[C_*BC_];

__device__ __forceinline__ float gelu_f(float x){ return 0.5f*x*(1.0f+erff(x*0.7071067811865475f)); }
__device__ __forceinline__ void split2(float x, fp16&h, fp16&l){
    h = __float2half_rn(x); l = __float2half_rn(x - __half2float(h));
}

__device__ __forceinline__ void cp16(fp16* sm, const fp16* gm, bool pred){
    uint32_t sa = (uint32_t)__cvta_generic_to_shared(sm);
    int sz = pred ? 16 : 0;
    asm volatile("cp.async.ca.shared.global [%0], [%1], 16, %2;" :: "r"(sa), "l"(gm), "r"(sz));
}
#define CP_COMMIT() asm volatile("cp.async.commit_group;")

__device__ __forceinline__ void stage_tile(const fp16* __restrict__ src, int ld,
        int row0, int rmax, int k0, int K, fp16* sm, int tid, int rows){
    for (int i = tid; i < rows*4; i += 256){
        int r = i>>2, cq = i&3;
        int gr = row0 + r, gk = k0 + (cq<<3);
        bool p = (gr < rmax && gk < K);
        cp16(sm + r*40 + (cq<<3), p ? src + (size_t)gr*ld + gk : src, p);
    }
}
__device__ __forceinline__ void stage_conv(const fp16* __restrict__ src, int row0, int k0,
        fp16* sm, int tid){
    int ky = k0/1536, kxr = k0 - ky*1536, kx = kxr>>9, ci0 = kxr&511;
    for (int i = tid; i < 512; i += 256){
        int r = i>>2, cq = i&3;
        int gr = row0 + r;
        bool p = false; const fp16* g = src;
        if (gr < M_){
            int b = gr/S_, rem = gr - b*S_, h = rem/28, w = rem - h*28;
            int ih = h+ky-1, iw = w+kx-1;
            if ((unsigned)ih<28u && (unsigned)iw<28u){
                p = true; g = src + ((size_t)((b*28+ih)*28+iw))*BC_ + ci0 + (cq<<3);
            }
        }
        cp16(sm + r*40 + (cq<<3), g, p);
    }
}

// fp16x2 wmma GEMM: D = (Ah+Al)@Bh^T, 2-stage cp.async pipeline. B given as [N,K].
// EPI 0: fp32(+bias)  1: gelu->split  2: +bias+res->fp32  3: +bh+bw -> fp16 to o1
// EPI 5: +bias+res->fp32 AND split
// EPI 6 (qkv): col<1024 -> split(v*0.125) to qh/ql; <2048 -> kh fp16; else v fp32
template<int BN, int EPI, int GATHER>
__global__ void __launch_bounds__(256) mma_gemm(
    const fp16* __restrict__ Ah, const fp16* __restrict__ Al,
    const fp16* __restrict__ Bh,
    float* __restrict__ o0, fp16* __restrict__ o1, fp16* __restrict__ o2,
    fp16* __restrict__ o3,
    int M, int N, int K, int lda, int ldb, int ldc,
    long long sA, long long sB, long long sC,
    const float* __restrict__ bias, const float* __restrict__ res, int ldres,
    const float* __restrict__ bhp, const float* __restrict__ bwp)
{
    constexpr int BM = 128;
    constexpr int WarpsN = 4, WarpsM = 2;
    constexpr int WM = BM/WarpsM, WN = BN/WarpsN;
    constexpr int MI = WM/16, NI = WN/16;
    constexpr int ATILE = BM*40, BTILE = BN*40;
    constexpr int STAGE = 2*ATILE + BTILE;
    extern __shared__ __align__(128) fp16 pool[];

    const int tid = threadIdx.x, warp = tid>>5, lane = tid&31;
    const int bm = blockIdx.x*BM, bn = blockIdx.y*BN, g = blockIdx.z;
    Ah += (size_t)g*sA; Al += (size_t)g*sA; Bh += (size_t)g*sB;
    const int wrow = (warp/WarpsN)*WM, wcol = (warp%WarpsN)*WN;

    wmma::fragment<wmma::accumulator,16,16,16,float> acc[MI][NI];
    #pragma unroll
    for (int mi=0; mi<MI; mi++)
        #pragma unroll
        for (int ni=0; ni<NI; ni++) wmma::fill_fragment(acc[mi][ni], 0.f);

    const int KC = (K+31)>>5;
    auto issue = [&](int kc, int s){
        fp16* st = pool + s*STAGE;
        int k0 = kc<<5;
        if (GATHER){ stage_conv(Ah, bm, k0, st, tid); stage_conv(Al, bm, k0, st+ATILE, tid); }
        else { stage_tile(Ah, lda, bm, M, k0, K, st, tid, BM);
               stage_tile(Al, lda, bm, M, k0, K, st+ATILE, tid, BM); }
        stage_tile(Bh, ldb, bn, N, k0, K, st+2*ATILE, tid, BN);
        CP_COMMIT();
    };
    issue(0, 0);
    for (int kc = 0; kc < KC; kc++){
        int buf = kc & 1;
        if (kc+1 < KC){
            issue(kc+1, buf^1);
            asm volatile("cp.async.wait_group 1;");
        } else {
            asm volatile("cp.async.wait_group 0;");
        }
        __syncthreads();
        fp16 *Ash = pool + buf*STAGE, *Asl = Ash + ATILE, *Bsh = Ash + 2*ATILE;
        #pragma unroll
        for (int ks=0; ks<2; ks++){
            wmma::fragment<wmma::matrix_b,16,16,16,fp16,wmma::col_major> bh_f[NI];
            #pragma unroll
            for (int ni=0; ni<NI; ni++)
                wmma::load_matrix_sync(bh_f[ni], Bsh + (wcol+ni*16)*40 + ks*16, 40);
            #pragma unroll
            for (int mi=0; mi<MI; mi++){
                wmma::fragment<wmma::matrix_a,16,16,16,fp16,wmma::row_major> ah_f, al_f;
                wmma::load_matrix_sync(ah_f, Ash + (wrow+mi*16)*40 + ks*16, 40);
                wmma::load_matrix_sync(al_f, Asl + (wrow+mi*16)*40 + ks*16, 40);
                #pragma unroll
                for (int ni=0; ni<NI; ni++){
                    wmma::mma_sync(acc[mi][ni], ah_f, bh_f[ni], acc[mi][ni]);
                    wmma::mma_sync(acc[mi][ni], al_f, bh_f[ni], acc[mi][ni]);
                }
            }
        }
        __syncthreads();
    }

    float* eb = reinterpret_cast<float*>(pool) + warp*320;   // 16x20
    #pragma unroll
    for (int mi=0; mi<MI; mi++){
        #pragma unroll
        for (int ni=0; ni<NI; ni++){
            wmma::store_matrix_sync(eb, acc[mi][ni], 20, wmma::mem_row_major);
            __syncwarp();
            int row0 = bm + wrow + mi*16, col0 = bn + wcol + ni*16;
            #pragma unroll
            for (int j=0; j<8; j++){
                int e = lane + j*32, r = e>>4, c = e&15;
                int gr = row0 + r, gc = col0 + c;
                if (gr < M && gc < N){
                    float v = eb[r*20 + c];
                    if (bias) v += bias[gc];
                    if (EPI == 1){ v = gelu_f(v); fp16 h,l; split2(v,h,l);
                        o1[(size_t)gr*ldc+gc]=h; o2[(size_t)gr*ldc+gc]=l; }
                    else if (EPI == 2){ o0[(size_t)gr*ldc+gc] = v + res[(size_t)gr*ldres+gc]; }
                    else if (EPI == 3){
                        v += bhp[((size_t)g*S_+gr)*28 + gc/28] + bwp[((size_t)g*S_+gr)*28 + gc%28];
                        o1[(size_t)g*sC + (size_t)gr*ldc + gc] = __float2half_rn(v); }
                    else if (EPI == 5){ v += res[(size_t)gr*ldres+gc];
                        o0[(size_t)gr*ldc+gc] = v; fp16 h,l; split2(v,h,l);
                        o1[(size_t)gr*ldc+gc]=h; o2[(size_t)gr*ldc+gc]=l; }
                    else if (EPI == 6){
                        int sec = gc >> 10, cc = gc & 1023;
                        int n = cc >> 6, d = cc & 63;
                        int b = gr / S_, s = gr - b*S_;
                        size_t o = ((size_t)((b<<4)+n)*S_ + s)*64 + d;
                        if (sec == 0){ fp16 h,l; split2(v*0.125f,h,l); o1[o]=h; o2[o]=l; }
                        else if (sec == 1){ o3[o] = __float2half_rn(v); }
                        else { o0[(size_t)gr*1024 + cc] = v; }
                    }
                    else o0[(size_t)gr*ldc+gc] = v;
                }
            }
            __syncwarp();
        }
    }
}

// fused stats + softmax + AV on fp16 scores (16B vectorized)
__global__ void __launch_bounds__(256) av_k(
    const fp16* __restrict__ attn,
    const fp16* __restrict__ vT, fp16* __restrict__ oh, fp16* __restrict__ ol)
{
    constexpr int KC = 25;
    __shared__ __align__(16) fp16 Ph[2][128*40], Pl[2][128*40], Vs[2][64*40];
    __shared__ float2 st[128];
    const int tid = threadIdx.x, warp = tid>>5, lane = tid&31;
    const int bm = blockIdx.x*128, g = blockIdx.y;
    attn += (size_t)g*S_*S_;
    vT   += (size_t)g*64*S_;
    const int wrow = (warp>>1)*32, wcol = (warp&1)*32;

    stage_tile(vT, S_, 0, 64, 0, S_, Vs[0], tid, 64);
    CP_COMMIT();

    // phase 0: per-row stats, 16B loads (8 halves); 784 = 98 uint4 per row
    for (int rr = 0; rr < 16; rr++){
        int r = warp*16 + rr;
        int grow = bm + r;
        if (grow < S_){
            const uint4* p = reinterpret_cast<const uint4*>(attn + (size_t)grow*S_);
            float vb[32];
            float m = -1e30f;
            #pragma unroll
            for (int i=0;i<4;i++){
                int idx = lane + i*32;
                uint4 u = (idx < 98) ? p[idx] : make_uint4(0,0,0,0);
                const fp16* hh = reinterpret_cast<const fp16*>(&u);
                #pragma unroll
                for (int t2=0;t2<8;t2++){
                    float v = (idx < 98) ? __half2float(hh[t2]) : -1e30f;
                    vb[i*8+t2] = v;
                    m = fmaxf(m, v);
                }
            }
            #pragma unroll
            for (int o=16;o;o>>=1) m = fmaxf(m, __shfl_xor_sync(~0u, m, o));
            float s = 0.f;
            #pragma unroll
            for (int i=0;i<4;i++){
                int idx = lane + i*32;
                if (idx < 98){
                    #pragma unroll
                    for (int t2=0;t2<8;t2++) s += __expf(vb[i*8+t2] - m);
                }
            }
            #pragma unroll
            for (int o=16;o;o>>=1) s += __shfl_xor_sync(~0u, s, o);
            if (lane == 0) st[r] = make_float2(m, 1.f/s);
        } else {
            if (lane == 0) st[r] = make_float2(0.f, 0.f);
        }
    }

    wmma::fragment<wmma::accumulator,16,16,16,float> acc[2][2];
    #pragma unroll
    for (int mi=0; mi<2; mi++)
        #pragma unroll
        for (int ni=0; ni<2; ni++) wmma::fill_fragment(acc[mi][ni], 0.f);

    uint4 areg[2];   // 8 halves each; 2 x 256 threads x 8 = 4096 = 128r x 32c
    auto loadA = [&](int kc){
        int k0 = kc<<5;
        #pragma unroll
        for (int j=0; j<2; j++){
            int sIdx = tid + j*256;
            int r = sIdx>>2, cq = sIdx&3;
            int row = bm + r, col = k0 + cq*8;
            if (row < S_ && col < S_)
                areg[j] = *reinterpret_cast<const uint4*>(attn + (size_t)row*S_ + col);
            else areg[j] = make_uint4(0,0,0,0);
        }
    };
    loadA(0);
    __syncthreads();   // st[] ready

    for (int kc = 0; kc < KC; kc++){
        int buf = kc & 1;
        #pragma unroll
        for (int j=0; j<2; j++){
            int sIdx = tid + j*256;
            int r = sIdx>>2, cq = sIdx&3;
            float m = st[r].x, inv = st[r].y;
            int colbase = (kc<<5) + cq*8;
            bool cv = ((bm + r) < S_) && (colbase < S_);
            const fp16* ah = reinterpret_cast<const fp16*>(&areg[j]);
            union { fp16 h[8]; uint4 u; } ph, pl;
            #pragma unroll
            for (int u2=0; u2<8; u2++){
                float p = cv ? __expf(__half2float(ah[u2]) - m) * inv : 0.f;
                split2(p, ph.h[u2], pl.h[u2]);
            }
            *reinterpret_cast<uint4*>(&Ph[buf][r*40 + cq*8]) = ph.u;
            *reinterpret_cast<uint4*>(&Pl[buf][r*40 + cq*8]) = pl.u;
        }
        if (kc+1 < KC){
            loadA(kc+1);
            stage_tile(vT, S_, 0, 64, (kc+1)<<5, S_, Vs[buf^1], tid, 64);
            CP_COMMIT();
            asm volatile("cp.async.wait_group 1;");
        } else {
            asm volatile("cp.async.wait_group 0;");
        }
        __syncthreads();
        #pragma unroll
        for (int ks=0; ks<2; ks++){
            wmma::fragment<wmma::matrix_b,16,16,16,fp16,wmma::col_major> b_f[2];
            #pragma unroll
            for (int ni=0; ni<2; ni++)
                wmma::load_matrix_sync(b_f[ni], Vs[buf] + (wcol+ni*16)*40 + ks*16, 40);
            #pragma unroll
            for (int mi=0; mi<2; mi++){
                wmma::fragment<wmma::matrix_a,16,16,16,fp16,wmma::row_major> ah_f, al_f;
                wmma::load_matrix_sync(ah_f, Ph[buf] + (wrow+mi*16)*40 + ks*16, 40);
                wmma::load_matrix_sync(al_f, Pl[buf] + (wrow+mi*16)*40 + ks*16, 40);
                #pragma unroll
                for (int ni=0; ni<2; ni++){
                    wmma::mma_sync(acc[mi][ni], ah_f, b_f[ni], acc[mi][ni]);
                    wmma::mma_sync(acc[mi][ni], al_f, b_f[ni], acc[mi][ni]);
                }
            }
        }
        __syncthreads();
    }

    float* eb = reinterpret_cast<float*>(Ph) + warp*320;
    #pragma unroll
    for (int mi=0; mi<2; mi++){
        #pragma unroll
        for (int ni=0; ni<2; ni++){
            wmma::store_matrix_sync(eb, acc[mi][ni], 20, wmma::mem_row_major);
            __syncwarp();
            int row0 = bm + wrow + mi*16, col0 = wcol + ni*16;
            #pragma unroll
            for (int j=0; j<8; j++){
                int e = lane + j*32, r = e>>4, c = e&15;
                int gr = row0 + r, gc = col0 + c;
                if (gr < S_){
                    size_t o = ((size_t)(g>>4)*S_ + gr)*1024 + (size_t)(g&15)*64 + gc;
                    fp16 h,l; split2(eb[r*20 + c], h, l);
                    oh[o]=h; ol[o]=l;
                }
            }
            __syncwarp();
        }
    }
}

__global__ void ln_k(const float* __restrict__ x, const float* __restrict__ w,
                     const float* __restrict__ bp, float* __restrict__ of,
                     fp16* __restrict__ oh, fp16* __restrict__ ol,
                     int Cw, float eps, int mode, const float* __restrict__ res)
{
    __shared__ float r1[8], r2[8], st[2];
    const int row = blockIdx.x, tid = threadIdx.x, lane = tid&31, wd = tid>>5;
    const float* xr = x + (size_t)row*Cw;
    float s=0.f, sq=0.f;
    for (int i = tid; i < Cw; i += 256){ float t = xr[i]; s += t; sq += t*t; }
    #pragma unroll
    for (int o=16;o;o>>=1){ s+=__shfl_down_sync(~0u,s,o); sq+=__shfl_down_sync(~0u,sq,o); }
    if (lane==0){ r1[wd]=s; r2[wd]=sq; }
    __syncthreads();
    if (tid==0){ float S=0,Q=0; for(int i=0;i<8;i++){S+=r1[i];Q+=r2[i];}
        float m=S/Cw, v=Q/Cw-m*m; st[0]=m; st[1]=rsqrtf(v+eps); }
    __syncthreads();
    float mean=st[0], rstd=st[1];
    for (int i = tid; i < Cw; i += 256){
        float y = (xr[i]-mean)*rstd*w[i] + bp[i];
        if (mode==2) of[(size_t)row*Cw+i] = y + res[(size_t)row*Cw+i];
        else { if (mode==1) y = gelu_f(y);
            fp16 h,l; split2(y,h,l); oh[(size_t)row*Cw+i]=h; ol[(size_t)row*Cw+i]=l; }
    }
}

// v32 [B,S,NH*HD] -> vTh [g,d,s]   (g = b*16+n)
__global__ void repack_v(const float* __restrict__ v32, fp16* __restrict__ vTh)
{
    __shared__ float sv[32][65];
    const int g = blockIdx.y, s0 = blockIdx.x*32, b = g>>4, n = g&15, t = threadIdx.x;
    for (int e = t; e < 2048; e += 256){
        int sl = e>>6, d = e&63, s = s0+sl;
        if (s < S_)
            sv[sl][d] = v32[((size_t)(b*S_ + s))*1024 + n*64 + d];
    }
    __syncthreads();
    for (int e = t; e < 2048; e += 256){
        int d = e>>5, j = e&31, s = s0+j;
        if (s < S_)
            vTh[((size_t)g*64+d)*S_ + s] = __float2half_rn(sv[j][d]);
    }
}

// rel-pos bias from split q (q stored scaled by 0.125 -> multiply dots by 8)
__global__ void relbias_k(const fp16* __restrict__ qh, const fp16* __restrict__ ql,
                          const float* __restrict__ rh, const float* __restrict__ rw,
                          float* __restrict__ bh, float* __restrict__ bw)
{
    const int s = blockIdx.x % S_, g = blockIdx.x / S_;
    __shared__ float qs[64];
    const int t = threadIdx.x;
    size_t qo = ((size_t)g*S_ + s)*64 + t;
    qs[t] = (__half2float(qh[qo]) + __half2float(ql[qo])) * 8.0f;
    __syncthreads();
    const int h = s/28, w = s%28;
    if (t < 28){
        const float* r = rh + (size_t)(h-t+27)*64; float a=0.f;
        #pragma unroll
        for (int d=0;d<64;d++) a = fmaf(qs[d], r[d], a);
        bh[((size_t)g*S_+s)*28 + t] = a;
    } else if (t >= 32 && t < 60){
        const int l = t-32;
        const float* r = rw + (size_t)(w-l+27)*64; float a=0.f;
        #pragma unroll
        for (int d=0;d<64;d++) a = fmaf(qs[d], r[d], a);
        bw[((size_t)g*S_+s)*28 + l] = a;
    }
}

__global__ void wsplit_all(
    const float* s0, const float* s1, const float* s2, const float* s3,
    const float* s4, const float* s5, const float* s6,
    fp16* d0, fp16* d1, fp16* d2, fp16* d3, fp16* d4, fp16* d5, fp16* d6)
{
    int t = blockIdx.x;
    const float* src; fp16* dst; int K, N, loc;
    if      (t <  3072){ src=s0; dst=d0; K=C_;     N=3*C_;  loc=t; }
    else if (t <  4096){ src=s1; dst=d1; K=C_;     N=C_;    loc=t-3072; }
    else if (t <  8192){ src=s2; dst=d2; K=C_;     N=HID_;  loc=t-4096; }
    else if (t < 12288){ src=s3; dst=d3; K=HID_;   N=C_;    loc=t-8192; }
    else if (t < 12800){ src=s4; dst=d4; K=C_;     N=BC_;   loc=t-12288; }
    else if (t < 15104){ src=s5; dst=d5; K=9*BC_;  N=BC_;   loc=t-12800; }
    else               { src=s6; dst=d6; K=BC_;    N=C_;    loc=t-15104; }
    int kt = K >> 5;
    int k0 = (loc % kt) * 32, n0 = (loc / kt) * 32;

    __shared__ float s[32][33];
    const int tx = threadIdx.x, ty = threadIdx.y;
    #pragma unroll
    for (int y=0;y<32;y+=8) s[ty+y][tx] = src[(size_t)(k0+ty+y)*N + n0+tx];
    __syncthreads();
    #pragma unroll
    for (int y=0;y<32;y+=8)
        dst[(size_t)(n0+ty+y)*K + k0+tx] = __float2half_rn(s[tx][ty+y]);
}

constexpr int SM128 = (2*128*40 + 128*40)*2*2;   // 61440 B
#define GSA(p, sym) cudaGetSymbolAddress((void**)&p, sym)
extern "C" void kernel_launch(void* const* d_in, const int* in_sizes, int n_in,
                              void* d_out, int out_size)
{
    const float *x=(const float*)d_in[0], *n1w=(const float*)d_in[1], *n1b=(const float*)d_in[2],
        *qkvw=(const float*)d_in[3], *qkvb=(const float*)d_in[4], *pw=(const float*)d_in[5],
        *pb=(const float*)d_in[6], *relh=(const float*)d_in[7], *relw=(const float*)d_in[8],
        *n2w=(const float*)d_in[9], *n2b=(const float*)d_in[10], *f1w=(const float*)d_in[11],
        *f1b=(const float*)d_in[12], *f2w=(const float*)d_in[13], *f2b=(const float*)d_in[14],
        *c1w=(const float*)d_in[15], *l1w=(const float*)d_in[16], *l1b=(const float*)d_in[17],
        *c2w=(const float*)d_in[18], *l2w=(const float*)d_in[19], *l2b=(const float*)d_in[20],
        *c3w=(const float*)d_in[21], *l3w=(const float*)d_in[22], *l3b=(const float*)d_in[23];
    float* out = (float*)d_out;

    float *v32,*bh,*bw,*x1,*x2,*c1,*c2,*c3;
    fp16 *attn;
    fp16 *xnh,*xnl,*qh,*ql,*kh,*vTh,*aoh,*aol,*mh,*ml,*x2h,*x2l,*c1h,*c1l,*c2h,*c2l;
    fp16 *wah,*wbh,*wch,*wdh,*weh,*wfh,*wgh;
    GSA(v32,g_v32); GSA(bh,g_bh); GSA(bw,g_bw); GSA(attn,g_attn); GSA(x1,g_x1); GSA(x2,g_x2);
    GSA(c1,g_c1); GSA(c2,g_c2); GSA(c3,g_c3);
    GSA(xnh,g_xnh); GSA(xnl,g_xnl); GSA(qh,g_qh); GSA(ql,g_ql); GSA(kh,g_kh);
    GSA(vTh,g_vTh); GSA(aoh,g_aoh); GSA(aol,g_aol);
    GSA(mh,g_mh); GSA(ml,g_ml); GSA(x2h,g_x2h); GSA(x2l,g_x2l);
    GSA(c1h,g_c1h); GSA(c1l,g_c1l); GSA(c2h,g_c2h); GSA(c2l,g_c2l);
    GSA(wah,g_wah); GSA(wbh,g_wbh); GSA(wch,g_wch); GSA(wdh,g_wdh);
    GSA(weh,g_weh); GSA(wfh,g_wfh); GSA(wgh,g_wgh);

    cudaFuncSetAttribute(mma_gemm<128,0,0>, cudaFuncAttributeMaxDynamicSharedMemorySize, SM128);
    cudaFuncSetAttribute(mma_gemm<128,1,0>, cudaFuncAttributeMaxDynamicSharedMemorySize, SM128);
    cudaFuncSetAttribute(mma_gemm<128,2,0>, cudaFuncAttributeMaxDynamicSharedMemorySize, SM128);
    cudaFuncSetAttribute(mma_gemm<128,3,0>, cudaFuncAttributeMaxDynamicSharedMemorySize, SM128);
    cudaFuncSetAttribute(mma_gemm<128,5,0>, cudaFuncAttributeMaxDynamicSharedMemorySize, SM128);
    cudaFuncSetAttribute(mma_gemm<128,6,0>, cudaFuncAttributeMaxDynamicSharedMemorySize, SM128);
    cudaFuncSetAttribute(mma_gemm<128,0,1>, cudaFuncAttributeMaxDynamicSharedMemorySize, SM128);

    wsplit_all<<<15616, dim3(32,8)>>>(qkvw, pw, f1w, f2w, c1w, c2w, c3w,
                                      wah, wbh, wch, wdh, weh, wfh, wgh);

    ln_k<<<M_,256>>>(x, n1w, n1b, nullptr, xnh, xnl, C_, 1e-5f, 0, nullptr);
    mma_gemm<128,6,0><<<dim3(49,24,1),256,SM128>>>(xnh,xnl,wah, v32,qh,ql,kh,
        M_,3*C_,C_, C_,C_,3*C_, 0,0,0, qkvb,nullptr,0,nullptr,nullptr);
    repack_v<<<dim3(25,G_),256>>>(v32, vTh);
    relbias_k<<<G_*S_,64>>>(qh,ql,relh,relw,bh,bw);
    mma_gemm<128,3,0><<<dim3(7,7,G_),256,SM128>>>(qh,ql,kh, nullptr,attn,nullptr,nullptr,
        S_,S_,64, 64,64,S_, (long long)S_*64,(long long)S_*64,(long long)S_*S_,
        nullptr,nullptr,0,bh,bw);
    av_k<<<dim3(7,G_),256>>>(attn, vTh, aoh, aol);
    mma_gemm<128,2,0><<<dim3(49,8,1),256,SM128>>>(aoh,aol,wbh, x1,nullptr,nullptr,nullptr,
        M_,C_,C_, C_,C_,C_, 0,0,0, pb,x,C_,nullptr,nullptr);
    ln_k<<<M_,256>>>(x1, n2w, n2b, nullptr, xnh, xnl, C_, 1e-5f, 0, nullptr);
    mma_gemm<128,1,0><<<dim3(49,32,1),256,SM128>>>(xnh,xnl,wch, nullptr,mh,ml,nullptr,
        M_,HID_,C_, C_,C_,HID_, 0,0,0, f1b,nullptr,0,nullptr,nullptr);
    mma_gemm<128,5,0><<<dim3(49,8,1),256,SM128>>>(mh,ml,wdh, x2,x2h,x2l,nullptr,
        M_,C_,HID_, HID_,HID_,C_, 0,0,0, f2b,x1,C_,nullptr,nullptr);
    mma_gemm<128,0,0><<<dim3(49,4,1),256,SM128>>>(x2h,x2l,weh, c1,nullptr,nullptr,nullptr,
        M_,BC_,C_, C_,C_,BC_, 0,0,0, nullptr,nullptr,0,nullptr,nullptr);
    ln_k<<<M_,256>>>(c1, l1w, l1b, nullptr, c1h, c1l, BC_, 1e-6f, 1, nullptr);
    mma_gemm<128,0,1><<<dim3(49,4,1),256,SM128>>>(c1h,c1l,wfh, c2,nullptr,nullptr,nullptr,
        M_,BC_,9*BC_, 0,9*BC_,BC_, 0,0,0, nullptr,nullptr,0,nullptr,nullptr);
    ln_k<<<M_,256>>>(c2, l2w, l2b, nullptr, c2h, c2l, BC_, 1e-6f, 1, nullptr);
    mma_gemm<128,0,0><<<dim3(49,8,1),256,SM128>>>(c2h,c2l,wgh, c3,nullptr,nullptr,nullptr,
        M_,C_,BC_, BC_,BC_,C_, 0,0,0, nullptr,nullptr,0,nullptr,nullptr);
    ln_k<<<M_,256>>>(c3, l3w, l3b, out, nullptr, nullptr, C_, 1e-6f, 2, x2);
}